// round 8
// baseline (speedup 1.0000x reference)
#include <cuda_runtime.h>
#include <cstdint>
#include <math.h>

#define BB 8
#define TT 512
#define CC 512
#define HH 8
#define DH 64
#define CF 2048
#define MTOK (BB*TT)      // 4096
#define VV 512
#define NSTEPS 4
#define ATT_SCALE 0.125f  // 1/sqrt(64)

// ---------------- scratch (device globals: no allocations allowed) ----------
__device__ float g_x [MTOK*CC];
__device__ float g_xn[MTOK*CC];
__device__ float g_q [MTOK*CC];
__device__ float g_k [MTOK*CC];
__device__ float g_v [MTOK*CC];
__device__ float g_y [MTOK*CC];
__device__ float g_h [MTOK*CF];
__device__ float g_att[(size_t)BB*HH*TT*TT];
// pre-rounded (tf32) weights
__device__ float g_wq[2*CC*CC];
__device__ float g_wk[2*CC*CC];
__device__ float g_wv[2*CC*CC];
__device__ float g_wp[2*CC*CC];
__device__ float g_w1[2*CC*CF];
__device__ float g_w2[2*CF*CC];
__device__ float g_wh[CC*VV];

// ======================= helpers ==============================
__device__ __forceinline__ uint32_t smem_u32(const void* p) {
    uint32_t a;
    asm("{ .reg .u64 t; cvta.to.shared.u64 t, %1; cvt.u32.u64 %0, t; }"
        : "=r"(a) : "l"(p));
    return a;
}
__device__ __forceinline__ void cp_async16(uint32_t dst, const void* src) {
    asm volatile("cp.async.cg.shared.global [%0], [%1], 16;" :: "r"(dst), "l"(src));
}
__device__ __forceinline__ void cp_commit() {
    asm volatile("cp.async.commit_group;" ::: "memory");
}
template <int N>
__device__ __forceinline__ void cp_wait() {
    asm volatile("cp.async.wait_group %0;" :: "n"(N) : "memory");
}
__device__ __forceinline__ uint32_t f2tf32(float x) {
    uint32_t r;
    asm("cvt.rna.tf32.f32 %0, %1;" : "=r"(r) : "f"(x));
    return r;
}
__device__ __forceinline__ float rndf(float x) { return __uint_as_float(f2tf32(x)); }
// D += A @ B  (m16n8k8, tf32 in, fp32 accumulate)
__device__ __forceinline__ void mma8(float* c, const uint32_t* a, const uint32_t* b) {
    asm volatile(
        "mma.sync.aligned.m16n8k8.row.col.f32.tf32.tf32.f32 "
        "{%0,%1,%2,%3}, {%4,%5,%6,%7}, {%8,%9}, {%0,%1,%2,%3};"
        : "+f"(c[0]), "+f"(c[1]), "+f"(c[2]), "+f"(c[3])
        : "r"(a[0]), "r"(a[1]), "r"(a[2]), "r"(a[3]), "r"(b[0]), "r"(b[1]));
}

// ---------------- weight pre-rounding (tf32) ----------------
__global__ void prep3_k(const float* __restrict__ a, const float* __restrict__ b,
                        const float* __restrict__ c, float* __restrict__ da,
                        float* __restrict__ db, float* __restrict__ dc, int n) {
    int i = blockIdx.x * 256 + threadIdx.x;
    if (i < n) { da[i] = rndf(a[i]); db[i] = rndf(b[i]); dc[i] = rndf(c[i]); }
}

// ================== dense GEMM: out = epi(A@W + bias + res) ================
// A, W pre-rounded tf32. CTA tile 64x128, 8 warps (2x4), warp tile 32x32,
// K-chunk 32, cp.async double buffered. NO cvt in mainloop.
#define AS_STR 36
#define BS_STR 136
#define GEMM_SMEM (2*64*AS_STR*4 + 2*32*BS_STR*4)   // 53248 B

template <bool GELU, bool ROUND>
__global__ void __launch_bounds__(256, 3)
mma_gemm_k(const float* __restrict__ A, const float* __restrict__ W,
           const float* __restrict__ bias, const float* __restrict__ res,
           float* __restrict__ out, int M, int N, int K) {
    extern __shared__ char dsm[];
    float* As = (float*)dsm;                       // [2][64][AS_STR]
    float* Bs = As + 2 * 64 * AS_STR;              // [2][32][BS_STR]

    int tid = threadIdx.x;
    int wid = tid >> 5, lane = tid & 31;
    int g = lane >> 2, t = lane & 3;
    int mw = wid >> 2, nw = wid & 3;               // warp grid 2x4, tile 32x32
    int m0 = blockIdx.y * 64, n0 = blockIdx.x * 128;

    auto loadA = [&](int chunk, int buf) {
        const float* src = A + (size_t)m0 * K + chunk * 32;
        float* dst = As + buf * 64 * AS_STR;
        #pragma unroll
        for (int i = 0; i < 2; i++) {              // 64 rows x 8 segs = 512 tasks
            int c = tid + i * 256;
            int m = c >> 3, s = c & 7;
            cp_async16(smem_u32(dst + m * AS_STR + s * 4),
                       src + (size_t)m * K + s * 4);
        }
    };
    auto loadB = [&](int chunk, int buf) {
        const float* src = W + (size_t)(chunk * 32) * N + n0;
        float* dst = Bs + buf * 32 * BS_STR;
        #pragma unroll
        for (int i = 0; i < 4; i++) {              // 32 rows x 32 segs = 1024 tasks
            int c = tid + i * 256;
            int k = c >> 5, s = c & 31;
            cp_async16(smem_u32(dst + k * BS_STR + s * 4),
                       src + (size_t)k * N + s * 4);
        }
    };

    float acc[2][4][4];
    #pragma unroll
    for (int mi = 0; mi < 2; mi++)
        #pragma unroll
        for (int ni = 0; ni < 4; ni++)
            #pragma unroll
            for (int q = 0; q < 4; q++) acc[mi][ni][q] = 0.0f;

    const int nch = K >> 5;
    loadA(0, 0); loadB(0, 0); cp_commit();

    for (int i = 0; i < nch; i++) {
        int buf = i & 1;
        if (i + 1 < nch) {
            loadA(i + 1, buf ^ 1); loadB(i + 1, buf ^ 1); cp_commit();
            cp_wait<1>();
        } else {
            cp_wait<0>();
        }
        __syncthreads();
        const float* Ab = As + buf * 64 * AS_STR;
        const float* Bb = Bs + buf * 32 * BS_STR;
        #pragma unroll
        for (int ks = 0; ks < 4; ks++) {
            int k0 = ks * 8;
            uint32_t af[2][4], bf[4][2];
            #pragma unroll
            for (int mi = 0; mi < 2; mi++) {
                int row = mw * 32 + mi * 16;
                af[mi][0] = __float_as_uint(Ab[(row + g)     * AS_STR + k0 + t]);
                af[mi][1] = __float_as_uint(Ab[(row + 8 + g) * AS_STR + k0 + t]);
                af[mi][2] = __float_as_uint(Ab[(row + g)     * AS_STR + k0 + t + 4]);
                af[mi][3] = __float_as_uint(Ab[(row + 8 + g) * AS_STR + k0 + t + 4]);
            }
            #pragma unroll
            for (int ni = 0; ni < 4; ni++) {
                int col = nw * 32 + ni * 8 + g;
                bf[ni][0] = __float_as_uint(Bb[(k0 + t)     * BS_STR + col]);
                bf[ni][1] = __float_as_uint(Bb[(k0 + t + 4) * BS_STR + col]);
            }
            #pragma unroll
            for (int mi = 0; mi < 2; mi++)
                #pragma unroll
                for (int ni = 0; ni < 4; ni++)
                    mma8(acc[mi][ni], af[mi], bf[ni]);
        }
        __syncthreads();
    }

    // epilogue
    #pragma unroll
    for (int mi = 0; mi < 2; mi++) {
        #pragma unroll
        for (int ni = 0; ni < 4; ni++) {
            int r0  = m0 + mw * 32 + mi * 16 + g;
            int col = n0 + nw * 32 + ni * 8 + 2 * t;
            #pragma unroll
            for (int hh = 0; hh < 2; hh++) {
                int r = r0 + 8 * hh;
                #pragma unroll
                for (int q = 0; q < 2; q++) {
                    float v = acc[mi][ni][2 * hh + q];
                    int c = col + q;
                    if (bias) v += bias[c];
                    if (res)  v += res[(size_t)r * N + c];
                    if (GELU) v = 0.5f * v * (1.0f + erff(v * 0.70710678118654752f));
                    if (ROUND) v = rndf(v);
                    out[(size_t)r * N + c] = v;
                }
            }
        }
    }
}

// ============ attention scores: S = (Q Kt) * scale via mma ================
// Q,K pre-rounded by QKV GEMM epilogues. CTA tile 128x128, full K=64 resident.
#define QS_STR 68
#define SC_SMEM (2*128*QS_STR*4)                   // 69632 B

__global__ void __launch_bounds__(256)
attn_scores_k() {
    extern __shared__ char dsm[];
    float* Qs = (float*)dsm;                       // [128][QS_STR]
    float* Ks = Qs + 128 * QS_STR;                 // [128][QS_STR]

    int tid = threadIdx.x;
    int wid = tid >> 5, lane = tid & 31;
    int g = lane >> 2, t = lane & 3;
    int mw = wid >> 2, nw = wid & 3;
    int z = blockIdx.z;                            // b*H + h
    int b = z >> 3, h = z & 7;
    int qt = blockIdx.y * 128, kt = blockIdx.x * 128;

    const float* qb = g_q + ((size_t)b * TT) * CC + h * DH;
    const float* kb = g_k + ((size_t)b * TT) * CC + h * DH;
    #pragma unroll
    for (int i = 0; i < 8; i++) {
        int c = tid + i * 256;                     // 128 rows x 16 segs
        int r = c >> 4, s = c & 15;
        cp_async16(smem_u32(Qs + r * QS_STR + s * 4),
                   qb + (size_t)(qt + r) * CC + s * 4);
        cp_async16(smem_u32(Ks + r * QS_STR + s * 4),
                   kb + (size_t)(kt + r) * CC + s * 4);
    }
    cp_commit(); cp_wait<0>();
    __syncthreads();

    float acc[4][4][4] = {};
    #pragma unroll
    for (int ks = 0; ks < 8; ks++) {
        int k0 = ks * 8;
        uint32_t af[4][4], bf[4][2];
        #pragma unroll
        for (int mi = 0; mi < 4; mi++) {
            int row = mw * 64 + mi * 16;
            af[mi][0] = __float_as_uint(Qs[(row + g)     * QS_STR + k0 + t]);
            af[mi][1] = __float_as_uint(Qs[(row + 8 + g) * QS_STR + k0 + t]);
            af[mi][2] = __float_as_uint(Qs[(row + g)     * QS_STR + k0 + t + 4]);
            af[mi][3] = __float_as_uint(Qs[(row + 8 + g) * QS_STR + k0 + t + 4]);
        }
        #pragma unroll
        for (int ni = 0; ni < 4; ni++) {
            int col = nw * 32 + ni * 8 + g;        // K row = score column
            bf[ni][0] = __float_as_uint(Ks[col * QS_STR + k0 + t]);
            bf[ni][1] = __float_as_uint(Ks[col * QS_STR + k0 + t + 4]);
        }
        #pragma unroll
        for (int mi = 0; mi < 4; mi++)
            #pragma unroll
            for (int ni = 0; ni < 4; ni++)
                mma8(acc[mi][ni], af[mi], bf[ni]);
    }

    float* op = g_att + (size_t)z * TT * TT;
    #pragma unroll
    for (int mi = 0; mi < 4; mi++)
        #pragma unroll
        for (int ni = 0; ni < 4; ni++) {
            int r0  = qt + mw * 64 + mi * 16 + g;
            int col = kt + nw * 32 + ni * 8 + 2 * t;
            op[(size_t)r0       * TT + col]     = acc[mi][ni][0] * ATT_SCALE;
            op[(size_t)r0       * TT + col + 1] = acc[mi][ni][1] * ATT_SCALE;
            op[(size_t)(r0 + 8) * TT + col]     = acc[mi][ni][2] * ATT_SCALE;
            op[(size_t)(r0 + 8) * TT + col + 1] = acc[mi][ni][3] * ATT_SCALE;
        }
}

// ---------------- block reductions ----------------
__device__ __forceinline__ float block_reduce_sum(float v, float* sm) {
    #pragma unroll
    for (int o = 16; o; o >>= 1) v += __shfl_xor_sync(0xffffffffu, v, o);
    int w = threadIdx.x >> 5;
    if ((threadIdx.x & 31) == 0) sm[w] = v;
    __syncthreads();
    if (threadIdx.x < 32) {
        float x = (threadIdx.x < 8) ? sm[threadIdx.x] : 0.0f;
        #pragma unroll
        for (int o = 4; o; o >>= 1) x += __shfl_xor_sync(0xffffffffu, x, o);
        if (threadIdx.x == 0) sm[0] = x;
    }
    __syncthreads();
    float r = sm[0];
    __syncthreads();
    return r;
}
__device__ __forceinline__ float block_reduce_max(float v, float* sm) {
    #pragma unroll
    for (int o = 16; o; o >>= 1) v = fmaxf(v, __shfl_xor_sync(0xffffffffu, v, o));
    int w = threadIdx.x >> 5;
    if ((threadIdx.x & 31) == 0) sm[w] = v;
    __syncthreads();
    if (threadIdx.x < 32) {
        float x = (threadIdx.x < 8) ? sm[threadIdx.x] : -1e30f;
        #pragma unroll
        for (int o = 4; o; o >>= 1) x = fmaxf(x, __shfl_xor_sync(0xffffffffu, x, o));
        if (threadIdx.x == 0) sm[0] = x;
    }
    __syncthreads();
    float r = sm[0];
    __syncthreads();
    return r;
}

// ---------------- softmax (writes tf32-rounded probabilities) --------------
__global__ void softmax_k() {
    __shared__ float sm[8];
    size_t row = blockIdx.x;
    float* p = g_att + row * TT;
    int t = threadIdx.x;
    float v0 = p[t], v1 = p[t + 256];
    float mx = block_reduce_max(fmaxf(v0, v1), sm);
    float e0 = expf(v0 - mx), e1 = expf(v1 - mx);
    float s = block_reduce_sum(e0 + e1, sm);
    float inv = 1.0f / s;
    p[t]       = rndf(e0 * inv);
    p[t + 256] = rndf(e1 * inv);
}

// ============ Y = P @ V via mma: per (b,h) [512,512]@[512,64] ==============
#define PS_STR 68
#define VS_STR 72
#define PV_SMEM (128*PS_STR*4 + 64*VS_STR*4)       // 53248 B

__global__ void __launch_bounds__(256)
attn_pv_k() {
    extern __shared__ char dsm[];
    float* Ps = (float*)dsm;                       // [128][PS_STR]
    float* Vs = Ps + 128 * PS_STR;                 // [64][VS_STR]

    int tid = threadIdx.x;
    int wid = tid >> 5, lane = tid & 31;
    int g = lane >> 2, t = lane & 3;
    int mw = wid & 3, nw = wid >> 2;               // warp grid 4(m) x 2(n)
    int z = blockIdx.y;
    int b = z >> 3, h = z & 7;
    int qt = blockIdx.x * 128;

    const float* pb = g_att + (size_t)z * TT * TT;
    const float* vb = g_v + ((size_t)b * TT) * CC + h * DH;

    float acc[2][4][4] = {};

    for (int kc = 0; kc < 8; kc++) {               // K chunks of 64
        int kk0 = kc * 64;
        __syncthreads();
        #pragma unroll
        for (int i = 0; i < 8; i++) {              // P: 128 rows x 16 segs
            int c = tid + i * 256;
            int r = c >> 4, s = c & 15;
            cp_async16(smem_u32(Ps + r * PS_STR + s * 4),
                       pb + (size_t)(qt + r) * TT + kk0 + s * 4);
        }
        #pragma unroll
        for (int i = 0; i < 4; i++) {              // V: 64 rows x 16 segs
            int c = tid + i * 256;
            int r = c >> 4, s = c & 15;
            cp_async16(smem_u32(Vs + r * VS_STR + s * 4),
                       vb + (size_t)(kk0 + r) * CC + s * 4);
        }
        cp_commit(); cp_wait<0>();
        __syncthreads();

        #pragma unroll
        for (int ks = 0; ks < 8; ks++) {
            int k0 = ks * 8;
            uint32_t af[2][4], bf[4][2];
            #pragma unroll
            for (int mi = 0; mi < 2; mi++) {
                int row = mw * 32 + mi * 16;
                af[mi][0] = __float_as_uint(Ps[(row + g)     * PS_STR + k0 + t]);
                af[mi][1] = __float_as_uint(Ps[(row + 8 + g) * PS_STR + k0 + t]);
                af[mi][2] = __float_as_uint(Ps[(row + g)     * PS_STR + k0 + t + 4]);
                af[mi][3] = __float_as_uint(Ps[(row + 8 + g) * PS_STR + k0 + t + 4]);
            }
            #pragma unroll
            for (int ni = 0; ni < 4; ni++) {
                int col = nw * 32 + ni * 8 + g;
                bf[ni][0] = __float_as_uint(Vs[(k0 + t)     * VS_STR + col]);
                bf[ni][1] = __float_as_uint(Vs[(k0 + t + 4) * VS_STR + col]);
            }
            #pragma unroll
            for (int mi = 0; mi < 2; mi++)
                #pragma unroll
                for (int ni = 0; ni < 4; ni++)
                    mma8(acc[mi][ni], af[mi], bf[ni]);
        }
    }

    float* yb = g_y + ((size_t)b * TT) * CC + h * DH;
    #pragma unroll
    for (int mi = 0; mi < 2; mi++)
        #pragma unroll
        for (int ni = 0; ni < 4; ni++) {
            int r0  = qt + mw * 32 + mi * 16 + g;
            int col = nw * 32 + ni * 8 + 2 * t;
            yb[(size_t)r0       * CC + col]     = rndf(acc[mi][ni][0]);
            yb[(size_t)r0       * CC + col + 1] = rndf(acc[mi][ni][1]);
            yb[(size_t)(r0 + 8) * CC + col]     = rndf(acc[mi][ni][2]);
            yb[(size_t)(r0 + 8) * CC + col + 1] = rndf(acc[mi][ni][3]);
        }
}

// ---------------- embedding ----------------
__global__ void embed_k(const int* __restrict__ idx, const float* __restrict__ tok,
                        const float* __restrict__ pos) {
    int i = blockIdx.x * blockDim.x + threadIdx.x;
    int m = i / CC, c = i - m * CC;
    int t = m & (TT - 1);
    g_x[i] = tok[idx[m] * CC + c] + pos[t * CC + c];
}

// ---------------- layernorm (output rounded to tf32) ----------------
__global__ void ln_k(const float* __restrict__ in, const float* __restrict__ gam,
                     const float* __restrict__ bet, float* __restrict__ out) {
    __shared__ float sm[8];
    int row = blockIdx.x;
    const float* x = in + (size_t)row * CC;
    int t = threadIdx.x;
    float v0 = x[t], v1 = x[t + 256];
    float mean = block_reduce_sum(v0 + v1, sm) * (1.0f / CC);
    float d0 = v0 - mean, d1 = v1 - mean;
    float var = block_reduce_sum(d0 * d0 + d1 * d1, sm) * (1.0f / CC);
    float rstd = rsqrtf(var + 1e-5f);
    float* o = out + (size_t)row * CC;
    o[t]       = rndf(d0 * rstd * gam[t]       + bet[t]);
    o[t + 256] = rndf(d1 * rstd * gam[t + 256] + bet[t + 256]);
}

// ---------------- host orchestration ----------------
extern "C" void kernel_launch(void* const* d_in, const int* in_sizes, int n_in,
                              void* d_out, int out_size) {
    const int*   idx  = (const int*)  d_in[0];
    const float* tok  = (const float*)d_in[1];
    const float* pos  = (const float*)d_in[2];
    const float* ln1g = (const float*)d_in[3];
    const float* ln1b = (const float*)d_in[4];
    const float* Wq   = (const float*)d_in[5];
    const float* bq   = (const float*)d_in[6];
    const float* Wk   = (const float*)d_in[7];
    const float* bk   = (const float*)d_in[8];
    const float* Wv   = (const float*)d_in[9];
    const float* bv   = (const float*)d_in[10];
    const float* Wp   = (const float*)d_in[11];
    const float* bp   = (const float*)d_in[12];
    const float* ln2g = (const float*)d_in[13];
    const float* ln2b = (const float*)d_in[14];
    const float* W1   = (const float*)d_in[15];
    const float* b1   = (const float*)d_in[16];
    const float* W2   = (const float*)d_in[17];
    const float* b2   = (const float*)d_in[18];
    const float* lnfg = (const float*)d_in[19];
    const float* lnfb = (const float*)d_in[20];
    const float* Wh   = (const float*)d_in[21];
    float* out = (float*)d_out;

    float *px, *pxn, *pq, *pk, *pv, *py, *ph;
    float *pwq, *pwk, *pwv, *pwp, *pw1, *pw2, *pwh;
    cudaGetSymbolAddress((void**)&px,  g_x);
    cudaGetSymbolAddress((void**)&pxn, g_xn);
    cudaGetSymbolAddress((void**)&pq,  g_q);
    cudaGetSymbolAddress((void**)&pk,  g_k);
    cudaGetSymbolAddress((void**)&pv,  g_v);
    cudaGetSymbolAddress((void**)&py,  g_y);
    cudaGetSymbolAddress((void**)&ph,  g_h);
    cudaGetSymbolAddress((void**)&pwq, g_wq);
    cudaGetSymbolAddress((void**)&pwk, g_wk);
    cudaGetSymbolAddress((void**)&pwv, g_wv);
    cudaGetSymbolAddress((void**)&pwp, g_wp);
    cudaGetSymbolAddress((void**)&pw1, g_w1);
    cudaGetSymbolAddress((void**)&pw2, g_w2);
    cudaGetSymbolAddress((void**)&pwh, g_wh);

    cudaFuncSetAttribute(mma_gemm_k<false,false>,
                         cudaFuncAttributeMaxDynamicSharedMemorySize, GEMM_SMEM);
    cudaFuncSetAttribute(mma_gemm_k<false,true>,
                         cudaFuncAttributeMaxDynamicSharedMemorySize, GEMM_SMEM);
    cudaFuncSetAttribute(mma_gemm_k<true,true>,
                         cudaFuncAttributeMaxDynamicSharedMemorySize, GEMM_SMEM);
    cudaFuncSetAttribute(attn_scores_k,
                         cudaFuncAttributeMaxDynamicSharedMemorySize, SC_SMEM);
    cudaFuncSetAttribute(attn_pv_k,
                         cudaFuncAttributeMaxDynamicSharedMemorySize, PV_SMEM);

    // weight pre-rounding (tf32) — 3 launches total
    prep3_k<<<(2 * CC * CC + 255) / 256, 256>>>(Wq, Wk, Wv, pwq, pwk, pwv, 2 * CC * CC);
    prep3_k<<<(2 * CC * CF + 255) / 256, 256>>>(W1, W2, W1, pw1, pw2, pw1, 2 * CC * CF);
    prep3_k<<<(CC * VV + 255) / 256, 256>>>(Wp, Wp + CC * CC, Wh, pwp, pwp + CC * CC, pwh, CC * VV);

    embed_k<<<(MTOK * CC) / 256, 256>>>(idx, tok, pos);

    dim3 gCC(CC / 128, MTOK / 64);      // (4, 64)
    dim3 gCF(CF / 128, MTOK / 64);      // (16, 64)
    dim3 gS(4, 4, BB * HH);             // scores: 128x128 tiles
    dim3 gPV(4, BB * HH);               // pv: 128-row tiles

    for (int step = 0; step < NSTEPS; step++) {
        for (int l = 0; l < 2; l++) {
            size_t wo  = (size_t)l * CC * CC;
            size_t bo  = (size_t)l * CC;
            size_t w1o = (size_t)l * CC * CF;
            size_t b1o = (size_t)l * CF;

            ln_k<<<MTOK, 256>>>(px, ln1g + bo, ln1b + bo, pxn);
            mma_gemm_k<false,true><<<gCC, 256, GEMM_SMEM>>>(pxn, pwq + wo, bq + bo, nullptr, pq, MTOK, CC, CC);
            mma_gemm_k<false,true><<<gCC, 256, GEMM_SMEM>>>(pxn, pwk + wo, bk + bo, nullptr, pk, MTOK, CC, CC);
            mma_gemm_k<false,true><<<gCC, 256, GEMM_SMEM>>>(pxn, pwv + wo, bv + bo, nullptr, pv, MTOK, CC, CC);
            attn_scores_k<<<gS, 256, SC_SMEM>>>();
            softmax_k<<<BB * HH * TT, 256>>>();
            attn_pv_k<<<gPV, 256, PV_SMEM>>>();
            // x = x + y @ Wp + bp
            mma_gemm_k<false,false><<<gCC, 256, GEMM_SMEM>>>(py, pwp + wo, bp + bo, px, px, MTOK, CC, CC);

            ln_k<<<MTOK, 256>>>(px, ln2g + bo, ln2b + bo, pxn);
            mma_gemm_k<true,true><<<gCF, 256, GEMM_SMEM>>>(pxn, pw1 + w1o, b1 + b1o, nullptr, ph, MTOK, CF, CC);
            // x = x + h @ W2 + b2
            mma_gemm_k<false,false><<<gCC, 256, GEMM_SMEM>>>(ph, pw2 + w1o, b2 + bo, px, px, MTOK, CC, CF);
        }
    }

    ln_k<<<MTOK, 256>>>(px, lnfg, lnfb, pxn);
    mma_gemm_k<false,false><<<dim3(VV / 128, MTOK / 64), 256, GEMM_SMEM>>>(
        pxn, pwh, nullptr, nullptr, out, MTOK, VV, CC);
}

// round 9
// speedup vs baseline: 1.2648x; 1.2648x over previous
#include <cuda_runtime.h>
#include <cuda_fp16.h>
#include <cstdint>
#include <math.h>

#define BB 8
#define TT 512
#define CC 512
#define HH 8
#define DH 64
#define CF 2048
#define MTOK (BB*TT)      // 4096
#define VV 512
#define NSTEPS 4
#define ATT_SCALE 0.125f  // 1/sqrt(64)

// ---------------- scratch (device globals) ----------------
__device__ float  g_x [MTOK*CC];
__device__ __half g_xn[MTOK*CC];
__device__ float  g_q [MTOK*CC];
__device__ float  g_k [MTOK*CC];
__device__ float  g_v [MTOK*CC];
__device__ __half g_y [MTOK*CC];
__device__ __half g_h [MTOK*CF];
__device__ float  g_att[(size_t)BB*HH*TT*TT];
// fp16 k-pair-packed weights: u32[kp*N+n] = (W[2kp][n], W[2kp+1][n])
__device__ uint32_t g_wq[2*(CC/2)*CC];
__device__ uint32_t g_wk[2*(CC/2)*CC];
__device__ uint32_t g_wv[2*(CC/2)*CC];
__device__ uint32_t g_wp[2*(CC/2)*CC];
__device__ uint32_t g_w1[2*(CC/2)*CF];
__device__ uint32_t g_w2[2*(CF/2)*CC];
__device__ uint32_t g_wh[(CC/2)*VV];

// ======================= helpers ==============================
__device__ __forceinline__ uint32_t smem_u32(const void* p) {
    uint32_t a;
    asm("{ .reg .u64 t; cvta.to.shared.u64 t, %1; cvt.u32.u64 %0, t; }"
        : "=r"(a) : "l"(p));
    return a;
}
__device__ __forceinline__ void cp_async16(uint32_t dst, const void* src) {
    asm volatile("cp.async.cg.shared.global [%0], [%1], 16;" :: "r"(dst), "l"(src));
}
__device__ __forceinline__ void cp_commit() {
    asm volatile("cp.async.commit_group;" ::: "memory");
}
template <int N>
__device__ __forceinline__ void cp_wait() {
    asm volatile("cp.async.wait_group %0;" :: "n"(N) : "memory");
}
__device__ __forceinline__ uint32_t f2tf32(float x) {
    uint32_t r;
    asm("cvt.rna.tf32.f32 %0, %1;" : "=r"(r) : "f"(x));
    return r;
}
__device__ __forceinline__ float rndf(float x) { return __uint_as_float(f2tf32(x)); }
// tf32 m16n8k8 (attention)
__device__ __forceinline__ void mma8(float* c, const uint32_t* a, const uint32_t* b) {
    asm volatile(
        "mma.sync.aligned.m16n8k8.row.col.f32.tf32.tf32.f32 "
        "{%0,%1,%2,%3}, {%4,%5,%6,%7}, {%8,%9}, {%0,%1,%2,%3};"
        : "+f"(c[0]), "+f"(c[1]), "+f"(c[2]), "+f"(c[3])
        : "r"(a[0]), "r"(a[1]), "r"(a[2]), "r"(a[3]), "r"(b[0]), "r"(b[1]));
}
// fp16 m16n8k16 (dense GEMMs)
__device__ __forceinline__ void mma16(float* c, const uint32_t* a, const uint32_t* b) {
    asm volatile(
        "mma.sync.aligned.m16n8k16.row.col.f32.f16.f16.f32 "
        "{%0,%1,%2,%3}, {%4,%5,%6,%7}, {%8,%9}, {%0,%1,%2,%3};"
        : "+f"(c[0]), "+f"(c[1]), "+f"(c[2]), "+f"(c[3])
        : "r"(a[0]), "r"(a[1]), "r"(a[2]), "r"(a[3]), "r"(b[0]), "r"(b[1]));
}

// ---------------- weight packing: fp32 [K][N] -> u32 [(K/2)][N] ------------
__global__ void pack_w_k(const float* __restrict__ W, uint32_t* __restrict__ dst,
                         int K, int N) {
    int i = blockIdx.x * 256 + threadIdx.x;
    if (i >= (K / 2) * N) return;
    int kp = i / N, n = i - kp * N;
    __half lo = __float2half(W[(size_t)(2 * kp)     * N + n]);
    __half hi = __float2half(W[(size_t)(2 * kp + 1) * N + n]);
    dst[i] = (uint32_t)__half_as_ushort(lo) | ((uint32_t)__half_as_ushort(hi) << 16);
}

// ============ dense fp16 GEMM: out = epi(A@W + bias + res) =================
// A: __half [M][K] row-major. Wp: packed u32 [(K/2)][N]. CTA 128x128,
// 8 warps 2x4, warp tile 64x32, K-chunk 32 (two k16 mma steps), dbl buffered.
#define AS2 20    // u32 per A row (16 data + 4 pad)
#define BS2 136   // u32 per B kp-row (128 data + 8 pad)
#define GEMMH_SMEM (2*128*AS2*4 + 2*16*BS2*4)   // 37888 B

template <bool GELU, bool OUTHALF, bool ROUND>
__global__ void __launch_bounds__(256, 2)
hgemm_k(const __half* __restrict__ A, const uint32_t* __restrict__ Wp,
        const float* __restrict__ bias, const float* __restrict__ res,
        void* __restrict__ outv, int M, int N, int K) {
    extern __shared__ char dsm[];
    uint32_t* As = (uint32_t*)dsm;                 // [2][128][AS2]
    uint32_t* Bs = As + 2 * 128 * AS2;             // [2][16][BS2]

    int tid = threadIdx.x;
    int wid = tid >> 5, lane = tid & 31;
    int g = lane >> 2, t = lane & 3;
    int mw = wid >> 2, nw = wid & 3;               // warp grid 2x4
    int m0 = blockIdx.y * 128, n0 = blockIdx.x * 128;

    auto loadA = [&](int chunk, int buf) {
        const __half* src = A + (size_t)m0 * K + chunk * 32;
        uint32_t* dst = As + buf * 128 * AS2;
        #pragma unroll
        for (int i = 0; i < 2; i++) {              // 128 rows x 4 segs (16B=8 half)
            int c = tid + i * 256;
            int m = c >> 2, s = c & 3;
            cp_async16(smem_u32(dst + m * AS2 + s * 4),
                       src + (size_t)m * K + s * 8);
        }
    };
    auto loadB = [&](int chunk, int buf) {
        const uint32_t* src = Wp + (size_t)(chunk * 16) * N + n0;
        uint32_t* dst = Bs + buf * 16 * BS2;
        #pragma unroll
        for (int i = 0; i < 2; i++) {              // 16 kp-rows x 32 segs (16B=4 u32)
            int c = tid + i * 256;
            int k = c >> 5, s = c & 31;
            cp_async16(smem_u32(dst + k * BS2 + s * 4),
                       src + (size_t)k * N + s * 4);
        }
    };

    float acc[4][4][4];
    #pragma unroll
    for (int mi = 0; mi < 4; mi++)
        #pragma unroll
        for (int ni = 0; ni < 4; ni++)
            #pragma unroll
            for (int q = 0; q < 4; q++) acc[mi][ni][q] = 0.0f;

    const int nch = K >> 5;
    loadA(0, 0); loadB(0, 0); cp_commit();

    for (int i = 0; i < nch; i++) {
        int buf = i & 1;
        if (i + 1 < nch) {
            loadA(i + 1, buf ^ 1); loadB(i + 1, buf ^ 1); cp_commit();
            cp_wait<1>();
        } else {
            cp_wait<0>();
        }
        __syncthreads();
        const uint32_t* Ab = As + buf * 128 * AS2;
        const uint32_t* Bb = Bs + buf * 16 * BS2;
        #pragma unroll
        for (int s2 = 0; s2 < 2; s2++) {           // two k16 steps per chunk
            int kp0 = s2 * 8;
            uint32_t af[4][4], bf[4][2];
            #pragma unroll
            for (int mi = 0; mi < 4; mi++) {
                int row = mw * 64 + mi * 16;
                af[mi][0] = Ab[(row + g)     * AS2 + kp0 + t];
                af[mi][1] = Ab[(row + 8 + g) * AS2 + kp0 + t];
                af[mi][2] = Ab[(row + g)     * AS2 + kp0 + t + 4];
                af[mi][3] = Ab[(row + 8 + g) * AS2 + kp0 + t + 4];
            }
            #pragma unroll
            for (int ni = 0; ni < 4; ni++) {
                int col = nw * 32 + ni * 8 + g;
                bf[ni][0] = Bb[(kp0 + t)     * BS2 + col];
                bf[ni][1] = Bb[(kp0 + t + 4) * BS2 + col];
            }
            #pragma unroll
            for (int mi = 0; mi < 4; mi++)
                #pragma unroll
                for (int ni = 0; ni < 4; ni++)
                    mma16(acc[mi][ni], af[mi], bf[ni]);
        }
        __syncthreads();
    }

    // epilogue
    #pragma unroll
    for (int mi = 0; mi < 4; mi++) {
        #pragma unroll
        for (int ni = 0; ni < 4; ni++) {
            int r0  = m0 + mw * 64 + mi * 16 + g;
            int col = n0 + nw * 32 + ni * 8 + 2 * t;
            #pragma unroll
            for (int hh = 0; hh < 2; hh++) {
                int r = r0 + 8 * hh;
                #pragma unroll
                for (int q = 0; q < 2; q++) {
                    float v = acc[mi][ni][2 * hh + q];
                    int c = col + q;
                    if (bias) v += bias[c];
                    if (res)  v += res[(size_t)r * N + c];
                    if (GELU) v = 0.5f * v * (1.0f + erff(v * 0.70710678118654752f));
                    if (OUTHALF) {
                        ((__half*)outv)[(size_t)r * N + c] = __float2half(v);
                    } else {
                        if (ROUND) v = rndf(v);
                        ((float*)outv)[(size_t)r * N + c] = v;
                    }
                }
            }
        }
    }
}

// ============ attention scores (tf32, unchanged from R7) ==================
#define QS_STR 68
#define SC_SMEM (2*128*QS_STR*4)                   // 69632 B

__global__ void __launch_bounds__(256)
attn_scores_k() {
    extern __shared__ char dsm[];
    float* Qs = (float*)dsm;                       // [128][QS_STR]
    float* Ks = Qs + 128 * QS_STR;                 // [128][QS_STR]

    int tid = threadIdx.x;
    int wid = tid >> 5, lane = tid & 31;
    int g = lane >> 2, t = lane & 3;
    int mw = wid >> 2, nw = wid & 3;
    int z = blockIdx.z;                            // b*H + h
    int b = z >> 3, h = z & 7;
    int qt = blockIdx.y * 128, kt = blockIdx.x * 128;

    const float* qb = g_q + ((size_t)b * TT) * CC + h * DH;
    const float* kb = g_k + ((size_t)b * TT) * CC + h * DH;
    #pragma unroll
    for (int i = 0; i < 8; i++) {
        int c = tid + i * 256;                     // 128 rows x 16 segs
        int r = c >> 4, s = c & 15;
        cp_async16(smem_u32(Qs + r * QS_STR + s * 4),
                   qb + (size_t)(qt + r) * CC + s * 4);
        cp_async16(smem_u32(Ks + r * QS_STR + s * 4),
                   kb + (size_t)(kt + r) * CC + s * 4);
    }
    cp_commit(); cp_wait<0>();
    __syncthreads();

    float acc[4][4][4] = {};
    #pragma unroll
    for (int ks = 0; ks < 8; ks++) {
        int k0 = ks * 8;
        uint32_t af[4][4], bf[4][2];
        #pragma unroll
        for (int mi = 0; mi < 4; mi++) {
            int row = mw * 64 + mi * 16;
            af[mi][0] = __float_as_uint(Qs[(row + g)     * QS_STR + k0 + t]);
            af[mi][1] = __float_as_uint(Qs[(row + 8 + g) * QS_STR + k0 + t]);
            af[mi][2] = __float_as_uint(Qs[(row + g)     * QS_STR + k0 + t + 4]);
            af[mi][3] = __float_as_uint(Qs[(row + 8 + g) * QS_STR + k0 + t + 4]);
        }
        #pragma unroll
        for (int ni = 0; ni < 4; ni++) {
            int col = nw * 32 + ni * 8 + g;        // K row = score column
            bf[ni][0] = __float_as_uint(Ks[col * QS_STR + k0 + t]);
            bf[ni][1] = __float_as_uint(Ks[col * QS_STR + k0 + t + 4]);
        }
        #pragma unroll
        for (int mi = 0; mi < 4; mi++)
            #pragma unroll
            for (int ni = 0; ni < 4; ni++)
                mma8(acc[mi][ni], af[mi], bf[ni]);
    }

    float* op = g_att + (size_t)z * TT * TT;
    #pragma unroll
    for (int mi = 0; mi < 4; mi++)
        #pragma unroll
        for (int ni = 0; ni < 4; ni++) {
            int r0  = qt + mw * 64 + mi * 16 + g;
            int col = kt + nw * 32 + ni * 8 + 2 * t;
            op[(size_t)r0       * TT + col]     = acc[mi][ni][0] * ATT_SCALE;
            op[(size_t)r0       * TT + col + 1] = acc[mi][ni][1] * ATT_SCALE;
            op[(size_t)(r0 + 8) * TT + col]     = acc[mi][ni][2] * ATT_SCALE;
            op[(size_t)(r0 + 8) * TT + col + 1] = acc[mi][ni][3] * ATT_SCALE;
        }
}

// ---------------- block reductions ----------------
__device__ __forceinline__ float block_reduce_sum(float v, float* sm) {
    #pragma unroll
    for (int o = 16; o; o >>= 1) v += __shfl_xor_sync(0xffffffffu, v, o);
    int w = threadIdx.x >> 5;
    if ((threadIdx.x & 31) == 0) sm[w] = v;
    __syncthreads();
    if (threadIdx.x < 32) {
        float x = (threadIdx.x < 8) ? sm[threadIdx.x] : 0.0f;
        #pragma unroll
        for (int o = 4; o; o >>= 1) x += __shfl_xor_sync(0xffffffffu, x, o);
        if (threadIdx.x == 0) sm[0] = x;
    }
    __syncthreads();
    float r = sm[0];
    __syncthreads();
    return r;
}
__device__ __forceinline__ float block_reduce_max(float v, float* sm) {
    #pragma unroll
    for (int o = 16; o; o >>= 1) v = fmaxf(v, __shfl_xor_sync(0xffffffffu, v, o));
    int w = threadIdx.x >> 5;
    if ((threadIdx.x & 31) == 0) sm[w] = v;
    __syncthreads();
    if (threadIdx.x < 32) {
        float x = (threadIdx.x < 8) ? sm[threadIdx.x] : -1e30f;
        #pragma unroll
        for (int o = 4; o; o >>= 1) x = fmaxf(x, __shfl_xor_sync(0xffffffffu, x, o));
        if (threadIdx.x == 0) sm[0] = x;
    }
    __syncthreads();
    float r = sm[0];
    __syncthreads();
    return r;
}

// ---------------- softmax (tf32-rounded fp32 probs) ------------------------
__global__ void softmax_k() {
    __shared__ float sm[8];
    size_t row = blockIdx.x;
    float* p = g_att + row * TT;
    int t = threadIdx.x;
    float v0 = p[t], v1 = p[t + 256];
    float mx = block_reduce_max(fmaxf(v0, v1), sm);
    float e0 = expf(v0 - mx), e1 = expf(v1 - mx);
    float s = block_reduce_sum(e0 + e1, sm);
    float inv = 1.0f / s;
    p[t]       = rndf(e0 * inv);
    p[t + 256] = rndf(e1 * inv);
}

// ============ Y = P @ V (tf32; y written as __half) =======================
#define PS_STR 68
#define VS_STR 72
#define PV_SMEM (128*PS_STR*4 + 64*VS_STR*4)       // 53248 B

__global__ void __launch_bounds__(256)
attn_pv_k() {
    extern __shared__ char dsm[];
    float* Ps = (float*)dsm;                       // [128][PS_STR]
    float* Vs = Ps + 128 * PS_STR;                 // [64][VS_STR]

    int tid = threadIdx.x;
    int wid = tid >> 5, lane = tid & 31;
    int g = lane >> 2, t = lane & 3;
    int mw = wid & 3, nw = wid >> 2;               // warp grid 4(m) x 2(n)
    int z = blockIdx.y;
    int b = z >> 3, h = z & 7;
    int qt = blockIdx.x * 128;

    const float* pb = g_att + (size_t)z * TT * TT;
    const float* vb = g_v + ((size_t)b * TT) * CC + h * DH;

    float acc[2][4][4] = {};

    for (int kc = 0; kc < 8; kc++) {               // K chunks of 64
        int kk0 = kc * 64;
        __syncthreads();
        #pragma unroll
        for (int i = 0; i < 8; i++) {              // P: 128 rows x 16 segs
            int c = tid + i * 256;
            int r = c >> 4, s = c & 15;
            cp_async16(smem_u32(Ps + r * PS_STR + s * 4),
                       pb + (size_t)(qt + r) * TT + kk0 + s * 4);
        }
        #pragma unroll
        for (int i = 0; i < 4; i++) {              // V: 64 rows x 16 segs
            int c = tid + i * 256;
            int r = c >> 4, s = c & 15;
            cp_async16(smem_u32(Vs + r * VS_STR + s * 4),
                       vb + (size_t)(kk0 + r) * CC + s * 4);
        }
        cp_commit(); cp_wait<0>();
        __syncthreads();

        #pragma unroll
        for (int ks = 0; ks < 8; ks++) {
            int k0 = ks * 8;
            uint32_t af[2][4], bf[4][2];
            #pragma unroll
            for (int mi = 0; mi < 2; mi++) {
                int row = mw * 32 + mi * 16;
                af[mi][0] = __float_as_uint(Ps[(row + g)     * PS_STR + k0 + t]);
                af[mi][1] = __float_as_uint(Ps[(row + 8 + g) * PS_STR + k0 + t]);
                af[mi][2] = __float_as_uint(Ps[(row + g)     * PS_STR + k0 + t + 4]);
                af[mi][3] = __float_as_uint(Ps[(row + 8 + g) * PS_STR + k0 + t + 4]);
            }
            #pragma unroll
            for (int ni = 0; ni < 4; ni++) {
                int col = nw * 32 + ni * 8 + g;
                bf[ni][0] = __float_as_uint(Vs[(k0 + t)     * VS_STR + col]);
                bf[ni][1] = __float_as_uint(Vs[(k0 + t + 4) * VS_STR + col]);
            }
            #pragma unroll
            for (int mi = 0; mi < 2; mi++)
                #pragma unroll
                for (int ni = 0; ni < 4; ni++)
                    mma8(acc[mi][ni], af[mi], bf[ni]);
        }
    }

    __half* yb = g_y + ((size_t)b * TT) * CC + h * DH;
    #pragma unroll
    for (int mi = 0; mi < 2; mi++)
        #pragma unroll
        for (int ni = 0; ni < 4; ni++) {
            int r0  = qt + mw * 32 + mi * 16 + g;
            int col = nw * 32 + ni * 8 + 2 * t;
            *(__half2*)(yb + (size_t)r0       * CC + col) =
                __floats2half2_rn(acc[mi][ni][0], acc[mi][ni][1]);
            *(__half2*)(yb + (size_t)(r0 + 8) * CC + col) =
                __floats2half2_rn(acc[mi][ni][2], acc[mi][ni][3]);
        }
}

// ---------------- embedding ----------------
__global__ void embed_k(const int* __restrict__ idx, const float* __restrict__ tok,
                        const float* __restrict__ pos) {
    int i = blockIdx.x * blockDim.x + threadIdx.x;
    int m = i / CC, c = i - m * CC;
    int t = m & (TT - 1);
    g_x[i] = tok[idx[m] * CC + c] + pos[t * CC + c];
}

// ---------------- layernorm (writes __half) ----------------
__global__ void ln_k(const float* __restrict__ in, const float* __restrict__ gam,
                     const float* __restrict__ bet, __half* __restrict__ out) {
    __shared__ float sm[8];
    int row = blockIdx.x;
    const float* x = in + (size_t)row * CC;
    int t = threadIdx.x;
    float v0 = x[t], v1 = x[t + 256];
    float mean = block_reduce_sum(v0 + v1, sm) * (1.0f / CC);
    float d0 = v0 - mean, d1 = v1 - mean;
    float var = block_reduce_sum(d0 * d0 + d1 * d1, sm) * (1.0f / CC);
    float rstd = rsqrtf(var + 1e-5f);
    __half* o = out + (size_t)row * CC;
    o[t]       = __float2half(d0 * rstd * gam[t]       + bet[t]);
    o[t + 256] = __float2half(d1 * rstd * gam[t + 256] + bet[t + 256]);
}

// ---------------- host orchestration ----------------
extern "C" void kernel_launch(void* const* d_in, const int* in_sizes, int n_in,
                              void* d_out, int out_size) {
    const int*   idx  = (const int*)  d_in[0];
    const float* tok  = (const float*)d_in[1];
    const float* pos  = (const float*)d_in[2];
    const float* ln1g = (const float*)d_in[3];
    const float* ln1b = (const float*)d_in[4];
    const float* Wq   = (const float*)d_in[5];
    const float* bq   = (const float*)d_in[6];
    const float* Wk   = (const float*)d_in[7];
    const float* bk   = (const float*)d_in[8];
    const float* Wv   = (const float*)d_in[9];
    const float* bv   = (const float*)d_in[10];
    const float* Wp   = (const float*)d_in[11];
    const float* bp   = (const float*)d_in[12];
    const float* ln2g = (const float*)d_in[13];
    const float* ln2b = (const float*)d_in[14];
    const float* W1   = (const float*)d_in[15];
    const float* b1   = (const float*)d_in[16];
    const float* W2   = (const float*)d_in[17];
    const float* b2   = (const float*)d_in[18];
    const float* lnfg = (const float*)d_in[19];
    const float* lnfb = (const float*)d_in[20];
    const float* Wh   = (const float*)d_in[21];
    float* out = (float*)d_out;

    float *px, *pq, *pk, *pv;
    __half *pxn, *py, *ph;
    uint32_t *pwq, *pwk, *pwv, *pwp, *pw1, *pw2, *pwh;
    cudaGetSymbolAddress((void**)&px,  g_x);
    cudaGetSymbolAddress((void**)&pxn, g_xn);
    cudaGetSymbolAddress((void**)&pq,  g_q);
    cudaGetSymbolAddress((void**)&pk,  g_k);
    cudaGetSymbolAddress((void**)&pv,  g_v);
    cudaGetSymbolAddress((void**)&py,  g_y);
    cudaGetSymbolAddress((void**)&ph,  g_h);
    cudaGetSymbolAddress((void**)&pwq, g_wq);
    cudaGetSymbolAddress((void**)&pwk, g_wk);
    cudaGetSymbolAddress((void**)&pwv, g_wv);
    cudaGetSymbolAddress((void**)&pwp, g_wp);
    cudaGetSymbolAddress((void**)&pw1, g_w1);
    cudaGetSymbolAddress((void**)&pw2, g_w2);
    cudaGetSymbolAddress((void**)&pwh, g_wh);

    cudaFuncSetAttribute(hgemm_k<false,false,true>,
                         cudaFuncAttributeMaxDynamicSharedMemorySize, GEMMH_SMEM);
    cudaFuncSetAttribute(hgemm_k<false,false,false>,
                         cudaFuncAttributeMaxDynamicSharedMemorySize, GEMMH_SMEM);
    cudaFuncSetAttribute(hgemm_k<true,true,false>,
                         cudaFuncAttributeMaxDynamicSharedMemorySize, GEMMH_SMEM);
    cudaFuncSetAttribute(attn_scores_k,
                         cudaFuncAttributeMaxDynamicSharedMemorySize, SC_SMEM);
    cudaFuncSetAttribute(attn_pv_k,
                         cudaFuncAttributeMaxDynamicSharedMemorySize, PV_SMEM);

    // pack weights to fp16 k-pair format (per layer to avoid cross-layer pairs)
    for (int l = 0; l < 2; l++) {
        size_t wo  = (size_t)l * CC * CC;
        size_t wpo = (size_t)l * (CC / 2) * CC;
        pack_w_k<<<(CC / 2 * CC + 255) / 256, 256>>>(Wq + wo, pwq + wpo, CC, CC);
        pack_w_k<<<(CC / 2 * CC + 255) / 256, 256>>>(Wk + wo, pwk + wpo, CC, CC);
        pack_w_k<<<(CC / 2 * CC + 255) / 256, 256>>>(Wv + wo, pwv + wpo, CC, CC);
        pack_w_k<<<(CC / 2 * CC + 255) / 256, 256>>>(Wp + wo, pwp + wpo, CC, CC);
        pack_w_k<<<(CC / 2 * CF + 255) / 256, 256>>>(W1 + (size_t)l * CC * CF,
                                                     pw1 + (size_t)l * (CC / 2) * CF, CC, CF);
        pack_w_k<<<(CF / 2 * CC + 255) / 256, 256>>>(W2 + (size_t)l * CF * CC,
                                                     pw2 + (size_t)l * (CF / 2) * CC, CF, CC);
    }
    pack_w_k<<<(CC / 2 * VV + 255) / 256, 256>>>(Wh, pwh, CC, VV);

    embed_k<<<(MTOK * CC) / 256, 256>>>(idx, tok, pos);

    dim3 gCC(CC / 128, MTOK / 128);     // (4, 32)
    dim3 gCF(CF / 128, MTOK / 128);     // (16, 32)
    dim3 gS(4, 4, BB * HH);             // scores: 128x128 tiles
    dim3 gPV(4, BB * HH);               // pv: 128-row tiles

    for (int step = 0; step < NSTEPS; step++) {
        for (int l = 0; l < 2; l++) {
            size_t wpo = (size_t)l * (CC / 2) * CC;
            size_t bo  = (size_t)l * CC;
            size_t b1o = (size_t)l * CF;

            ln_k<<<MTOK, 256>>>(px, ln1g + bo, ln1b + bo, pxn);
            hgemm_k<false,false,true><<<gCC, 256, GEMMH_SMEM>>>(
                pxn, pwq + wpo, bq + bo, nullptr, pq, MTOK, CC, CC);
            hgemm_k<false,false,true><<<gCC, 256, GEMMH_SMEM>>>(
                pxn, pwk + wpo, bk + bo, nullptr, pk, MTOK, CC, CC);
            hgemm_k<false,false,true><<<gCC, 256, GEMMH_SMEM>>>(
                pxn, pwv + wpo, bv + bo, nullptr, pv, MTOK, CC, CC);
            attn_scores_k<<<gS, 256, SC_SMEM>>>();
            softmax_k<<<BB * HH * TT, 256>>>();
            attn_pv_k<<<gPV, 256, PV_SMEM>>>();
            // x = x + y @ Wp + bp
            hgemm_k<false,false,false><<<gCC, 256, GEMMH_SMEM>>>(
                py, pwp + wpo, bp + bo, px, px, MTOK, CC, CC);

            ln_k<<<MTOK, 256>>>(px, ln2g + bo, ln2b + bo, pxn);
            hgemm_k<true,true,false><<<gCF, 256, GEMMH_SMEM>>>(
                pxn, pw1 + (size_t)l * (CC / 2) * CF, b1 + b1o, nullptr, ph, MTOK, CF, CC);
            // x = x + h @ W2 + b2
            hgemm_k<false,false,false><<<gCC, 256, GEMMH_SMEM>>>(
                ph, pw2 + (size_t)l * (CF / 2) * CC, b2 + bo, px, px, MTOK, CC, CF);
        }
    }

    ln_k<<<MTOK, 256>>>(px, lnfg, lnfb, pxn);
    hgemm_k<false,false,false><<<dim3(VV / 128, MTOK / 128), 256, GEMMH_SMEM>>>(
        pxn, pwh, nullptr, nullptr, out, MTOK, VV, CC);
}

// round 11
// speedup vs baseline: 1.3299x; 1.0515x over previous
#include <cuda_runtime.h>
#include <cuda_fp16.h>
#include <cstdint>
#include <math.h>

#define BB 8
#define TT 512
#define CC 512
#define HH 8
#define DH 64
#define CF 2048
#define MTOK (BB*TT)      // 4096
#define VV 512
#define NSTEPS 4
#define ATT_SCALE 0.125f  // 1/sqrt(64)

// ---------------- scratch (device globals) ----------------
__device__ float  g_x [MTOK*CC];
__device__ __half g_xn[MTOK*CC];
__device__ __half g_qh[MTOK*CC];
__device__ __half g_kh[MTOK*CC];
__device__ __half g_vt[(size_t)BB*HH*DH*TT];   // V transposed: [z][dh][token]
__device__ __half g_y [MTOK*CC];
__device__ __half g_h [MTOK*CF];
__device__ float  g_att [(size_t)BB*HH*TT*TT]; // fp32 scores
__device__ __half g_attp[(size_t)BB*HH*TT*TT]; // fp16 probs
// fp16 k-pair-packed weights: u32[kp*N+n] = (W[2kp][n], W[2kp+1][n])
__device__ uint32_t g_wq[2*(CC/2)*CC];
__device__ uint32_t g_wk[2*(CC/2)*CC];
__device__ uint32_t g_wv[2*(CC/2)*CC];
__device__ uint32_t g_wp[2*(CC/2)*CC];
__device__ uint32_t g_w1[2*(CC/2)*CF];
__device__ uint32_t g_w2[2*(CF/2)*CC];
__device__ uint32_t g_wh[(CC/2)*VV];

// ======================= helpers ==============================
__device__ __forceinline__ uint32_t smem_u32(const void* p) {
    uint32_t a;
    asm("{ .reg .u64 t; cvta.to.shared.u64 t, %1; cvt.u32.u64 %0, t; }"
        : "=r"(a) : "l"(p));
    return a;
}
__device__ __forceinline__ void cp_async16(uint32_t dst, const void* src) {
    asm volatile("cp.async.cg.shared.global [%0], [%1], 16;" :: "r"(dst), "l"(src));
}
__device__ __forceinline__ void cp_commit() {
    asm volatile("cp.async.commit_group;" ::: "memory");
}
template <int N>
__device__ __forceinline__ void cp_wait() {
    asm volatile("cp.async.wait_group %0;" :: "n"(N) : "memory");
}
// fp16 m16n8k16, fp32 accumulate
__device__ __forceinline__ void mma16(float* c, const uint32_t* a, const uint32_t* b) {
    asm volatile(
        "mma.sync.aligned.m16n8k16.row.col.f32.f16.f16.f32 "
        "{%0,%1,%2,%3}, {%4,%5,%6,%7}, {%8,%9}, {%0,%1,%2,%3};"
        : "+f"(c[0]), "+f"(c[1]), "+f"(c[2]), "+f"(c[3])
        : "r"(a[0]), "r"(a[1]), "r"(a[2]), "r"(a[3]), "r"(b[0]), "r"(b[1]));
}

// ---------------- weight packing: fp32 [K][N] -> u32 [(K/2)][N] ------------
__global__ void pack_w_k(const float* __restrict__ W, uint32_t* __restrict__ dst,
                         int K, int N) {
    int i = blockIdx.x * 256 + threadIdx.x;
    if (i >= (K / 2) * N) return;
    int kp = i / N, n = i - kp * N;
    __half lo = __float2half(W[(size_t)(2 * kp)     * N + n]);
    __half hi = __float2half(W[(size_t)(2 * kp + 1) * N + n]);
    dst[i] = (uint32_t)__half_as_ushort(lo) | ((uint32_t)__half_as_ushort(hi) << 16);
}

// ============ dense fp16 GEMM: out = epi(A@W + bias + res) =================
// A: __half [M][K]. Wp: packed u32 [(K/2)][N]. CTA 128x128, 8 warps 2x4,
// warp tile 64x32, K-chunk 32 (two k16 steps), double buffered.
// OUT modes: 0 = fp32, 1 = fp16 row-major, 2 = fp16 V-transposed (g_vt)
#define AS2 20
#define BS2 136
#define GEMMH_SMEM (2*128*AS2*4 + 2*16*BS2*4)   // 37888 B

template <bool GELU, int OUTMODE>
__global__ void __launch_bounds__(256, 2)
hgemm_k(const __half* __restrict__ A, const uint32_t* __restrict__ Wp,
        const float* __restrict__ bias, const float* __restrict__ res,
        void* __restrict__ outv, int M, int N, int K) {
    extern __shared__ char dsm[];
    uint32_t* As = (uint32_t*)dsm;                 // [2][128][AS2]
    uint32_t* Bs = As + 2 * 128 * AS2;             // [2][16][BS2]

    int tid = threadIdx.x;
    int wid = tid >> 5, lane = tid & 31;
    int g = lane >> 2, t = lane & 3;
    int mw = wid >> 2, nw = wid & 3;
    int m0 = blockIdx.y * 128, n0 = blockIdx.x * 128;

    auto loadA = [&](int chunk, int buf) {
        const __half* src = A + (size_t)m0 * K + chunk * 32;
        uint32_t* dst = As + buf * 128 * AS2;
        #pragma unroll
        for (int i = 0; i < 2; i++) {
            int c = tid + i * 256;
            int m = c >> 2, s = c & 3;
            cp_async16(smem_u32(dst + m * AS2 + s * 4),
                       src + (size_t)m * K + s * 8);
        }
    };
    auto loadB = [&](int chunk, int buf) {
        const uint32_t* src = Wp + (size_t)(chunk * 16) * N + n0;
        uint32_t* dst = Bs + buf * 16 * BS2;
        #pragma unroll
        for (int i = 0; i < 2; i++) {
            int c = tid + i * 256;
            int k = c >> 5, s = c & 31;
            cp_async16(smem_u32(dst + k * BS2 + s * 4),
                       src + (size_t)k * N + s * 4);
        }
    };

    float acc[4][4][4];
    #pragma unroll
    for (int mi = 0; mi < 4; mi++)
        #pragma unroll
        for (int ni = 0; ni < 4; ni++)
            #pragma unroll
            for (int q = 0; q < 4; q++) acc[mi][ni][q] = 0.0f;

    const int nch = K >> 5;
    loadA(0, 0); loadB(0, 0); cp_commit();

    for (int i = 0; i < nch; i++) {
        int buf = i & 1;
        if (i + 1 < nch) {
            loadA(i + 1, buf ^ 1); loadB(i + 1, buf ^ 1); cp_commit();
            cp_wait<1>();
        } else {
            cp_wait<0>();
        }
        __syncthreads();
        const uint32_t* Ab = As + buf * 128 * AS2;
        const uint32_t* Bb = Bs + buf * 16 * BS2;
        #pragma unroll
        for (int s2 = 0; s2 < 2; s2++) {
            int kp0 = s2 * 8;
            uint32_t af[4][4], bf[4][2];
            #pragma unroll
            for (int mi = 0; mi < 4; mi++) {
                int row = mw * 64 + mi * 16;
                af[mi][0] = Ab[(row + g)     * AS2 + kp0 + t];
                af[mi][1] = Ab[(row + 8 + g) * AS2 + kp0 + t];
                af[mi][2] = Ab[(row + g)     * AS2 + kp0 + t + 4];
                af[mi][3] = Ab[(row + 8 + g) * AS2 + kp0 + t + 4];
            }
            #pragma unroll
            for (int ni = 0; ni < 4; ni++) {
                int col = nw * 32 + ni * 8 + g;
                bf[ni][0] = Bb[(kp0 + t)     * BS2 + col];
                bf[ni][1] = Bb[(kp0 + t + 4) * BS2 + col];
            }
            #pragma unroll
            for (int mi = 0; mi < 4; mi++)
                #pragma unroll
                for (int ni = 0; ni < 4; ni++)
                    mma16(acc[mi][ni], af[mi], bf[ni]);
        }
        __syncthreads();
    }

    // epilogue
    #pragma unroll
    for (int mi = 0; mi < 4; mi++) {
        #pragma unroll
        for (int ni = 0; ni < 4; ni++) {
            int r0  = m0 + mw * 64 + mi * 16 + g;
            int col = n0 + nw * 32 + ni * 8 + 2 * t;
            #pragma unroll
            for (int hh = 0; hh < 2; hh++) {
                int r = r0 + 8 * hh;
                #pragma unroll
                for (int q = 0; q < 2; q++) {
                    float v = acc[mi][ni][2 * hh + q];
                    int c = col + q;
                    if (bias) v += bias[c];
                    if (res)  v += res[(size_t)r * N + c];
                    if (GELU) v = 0.5f * v * (1.0f + erff(v * 0.70710678118654752f));
                    if (OUTMODE == 1) {
                        ((__half*)outv)[(size_t)r * N + c] = __float2half(v);
                    } else if (OUTMODE == 2) {
                        // V transposed: z = b*H + h, vt[z][dh][token]
                        int b = r >> 9, h = c >> 6;
                        int dh = c & 63, tok = r & (TT - 1);
                        ((__half*)outv)[(((size_t)(b * HH + h) * DH) + dh) * TT + tok] =
                            __float2half(v);
                    } else {
                        ((float*)outv)[(size_t)r * N + c] = v;
                    }
                }
            }
        }
    }
}

// ============ attention scores: fp16 mma, fp32 scores out ==================
// Q,K __half. CTA tile 128x128, K=64 fully resident (4 k16 steps).
#define QS2 36
#define SC_SMEM (2*128*QS2*4)                      // 36864 B

__global__ void __launch_bounds__(256, 2)
attn_scores_k() {
    extern __shared__ char dsm[];
    uint32_t* Qs = (uint32_t*)dsm;                 // [128][QS2]
    uint32_t* Ks = Qs + 128 * QS2;                 // [128][QS2]

    int tid = threadIdx.x;
    int wid = tid >> 5, lane = tid & 31;
    int g = lane >> 2, t = lane & 3;
    int mw = wid >> 2, nw = wid & 3;
    int z = blockIdx.z;                            // b*H + h
    int b = z >> 3, h = z & 7;
    int qt = blockIdx.y * 128, kt = blockIdx.x * 128;

    const __half* qb = g_qh + ((size_t)b * TT) * CC + h * DH;
    const __half* kb = g_kh + ((size_t)b * TT) * CC + h * DH;
    #pragma unroll
    for (int i = 0; i < 4; i++) {
        int c = tid + i * 256;                     // 128 rows x 8 segs (16B = 8 half)
        int r = c >> 3, s = c & 7;
        cp_async16(smem_u32(Qs + r * QS2 + s * 4),
                   qb + (size_t)(qt + r) * CC + s * 8);
        cp_async16(smem_u32(Ks + r * QS2 + s * 4),
                   kb + (size_t)(kt + r) * CC + s * 8);
    }
    cp_commit(); cp_wait<0>();
    __syncthreads();

    float acc[4][4][4] = {};
    #pragma unroll
    for (int s2 = 0; s2 < 4; s2++) {               // 4 x k16 covers K=64
        int kp0 = s2 * 8;
        uint32_t af[4][4], bf[4][2];
        #pragma unroll
        for (int mi = 0; mi < 4; mi++) {
            int row = mw * 64 + mi * 16;
            af[mi][0] = Qs[(row + g)     * QS2 + kp0 + t];
            af[mi][1] = Qs[(row + 8 + g) * QS2 + kp0 + t];
            af[mi][2] = Qs[(row + g)     * QS2 + kp0 + t + 4];
            af[mi][3] = Qs[(row + 8 + g) * QS2 + kp0 + t + 4];
        }
        #pragma unroll
        for (int ni = 0; ni < 4; ni++) {
            int col = nw * 32 + ni * 8 + g;        // K row = score column
            bf[ni][0] = Ks[col * QS2 + kp0 + t];
            bf[ni][1] = Ks[col * QS2 + kp0 + t + 4];
        }
        #pragma unroll
        for (int mi = 0; mi < 4; mi++)
            #pragma unroll
            for (int ni = 0; ni < 4; ni++)
                mma16(acc[mi][ni], af[mi], bf[ni]);
    }

    float* op = g_att + (size_t)z * TT * TT;
    #pragma unroll
    for (int mi = 0; mi < 4; mi++)
        #pragma unroll
        for (int ni = 0; ni < 4; ni++) {
            int r0  = qt + mw * 64 + mi * 16 + g;
            int col = kt + nw * 32 + ni * 8 + 2 * t;
            op[(size_t)r0       * TT + col]     = acc[mi][ni][0] * ATT_SCALE;
            op[(size_t)r0       * TT + col + 1] = acc[mi][ni][1] * ATT_SCALE;
            op[(size_t)(r0 + 8) * TT + col]     = acc[mi][ni][2] * ATT_SCALE;
            op[(size_t)(r0 + 8) * TT + col + 1] = acc[mi][ni][3] * ATT_SCALE;
        }
}

// ---------------- block reductions ----------------
__device__ __forceinline__ float block_reduce_sum(float v, float* sm) {
    #pragma unroll
    for (int o = 16; o; o >>= 1) v += __shfl_xor_sync(0xffffffffu, v, o);
    int w = threadIdx.x >> 5;
    if ((threadIdx.x & 31) == 0) sm[w] = v;
    __syncthreads();
    if (threadIdx.x < 32) {
        float x = (threadIdx.x < 8) ? sm[threadIdx.x] : 0.0f;
        #pragma unroll
        for (int o = 4; o; o >>= 1) x += __shfl_xor_sync(0xffffffffu, x, o);
        if (threadIdx.x == 0) sm[0] = x;
    }
    __syncthreads();
    float r = sm[0];
    __syncthreads();
    return r;
}
__device__ __forceinline__ float block_reduce_max(float v, float* sm) {
    #pragma unroll
    for (int o = 16; o; o >>= 1) v = fmaxf(v, __shfl_xor_sync(0xffffffffu, v, o));
    int w = threadIdx.x >> 5;
    if ((threadIdx.x & 31) == 0) sm[w] = v;
    __syncthreads();
    if (threadIdx.x < 32) {
        float x = (threadIdx.x < 8) ? sm[threadIdx.x] : -1e30f;
        #pragma unroll
        for (int o = 4; o; o >>= 1) x = fmaxf(x, __shfl_xor_sync(0xffffffffu, x, o));
        if (threadIdx.x == 0) sm[0] = x;
    }
    __syncthreads();
    float r = sm[0];
    __syncthreads();
    return r;
}

// ---------------- softmax: fp32 in (g_att), fp16 probs out (g_attp) --------
__global__ void softmax_k() {
    __shared__ float sm[8];
    size_t row = blockIdx.x;
    const float* p = g_att + row * TT;
    __half* po = g_attp + row * TT;
    int t = threadIdx.x;
    float v0 = p[t], v1 = p[t + 256];
    float mx = block_reduce_max(fmaxf(v0, v1), sm);
    float e0 = expf(v0 - mx), e1 = expf(v1 - mx);
    float s = block_reduce_sum(e0 + e1, sm);
    float inv = 1.0f / s;
    po[t]       = __float2half(e0 * inv);
    po[t + 256] = __float2half(e1 * inv);
}

// ============ Y = P @ V, fp16 mma: per (b,h) [512,512]@[512,64] ============
// P half from g_attp (A, k-packed along keys); V^T half from g_vt (B, cols=dh).
#define PS2 36
#define VS2 36
#define PV_SMEM (128*PS2*4 + 64*VS2*4)             // 27648 B

__global__ void __launch_bounds__(256, 2)
attn_pv_k() {
    extern __shared__ char dsm[];
    uint32_t* Ps = (uint32_t*)dsm;                 // [128][PS2]
    uint32_t* Vs = Ps + 128 * PS2;                 // [64][VS2]

    int tid = threadIdx.x;
    int wid = tid >> 5, lane = tid & 31;
    int g = lane >> 2, t = lane & 3;
    int mw = wid & 3, nw = wid >> 2;               // warp grid 4(m) x 2(n)
    int z = blockIdx.y;
    int b = z >> 3, h = z & 7;
    int qt = blockIdx.x * 128;

    const __half* pb = g_attp + (size_t)z * TT * TT;
    const __half* vt = g_vt + (size_t)z * DH * TT;

    float acc[2][4][4] = {};

    for (int kc = 0; kc < 8; kc++) {               // key chunks of 64
        int kk0 = kc * 64;
        __syncthreads();
        #pragma unroll
        for (int i = 0; i < 4; i++) {              // P: 128 rows x 8 segs
            int c = tid + i * 256;
            int r = c >> 3, s = c & 7;
            cp_async16(smem_u32(Ps + r * PS2 + s * 4),
                       pb + (size_t)(qt + r) * TT + kk0 + s * 8);
        }
        #pragma unroll
        for (int i = 0; i < 2; i++) {              // V^T: 64 dh-rows x 8 segs
            int c = tid + i * 256;
            int r = c >> 3, s = c & 7;
            cp_async16(smem_u32(Vs + r * VS2 + s * 4),
                       vt + (size_t)r * TT + kk0 + s * 8);
        }
        cp_commit(); cp_wait<0>();
        __syncthreads();

        #pragma unroll
        for (int s2 = 0; s2 < 4; s2++) {           // 4 x k16 covers 64 keys
            int kp0 = s2 * 8;
            uint32_t af[2][4], bf[4][2];
            #pragma unroll
            for (int mi = 0; mi < 2; mi++) {
                int row = mw * 32 + mi * 16;
                af[mi][0] = Ps[(row + g)     * PS2 + kp0 + t];
                af[mi][1] = Ps[(row + 8 + g) * PS2 + kp0 + t];
                af[mi][2] = Ps[(row + g)     * PS2 + kp0 + t + 4];
                af[mi][3] = Ps[(row + 8 + g) * PS2 + kp0 + t + 4];
            }
            #pragma unroll
            for (int ni = 0; ni < 4; ni++) {
                int col = nw * 32 + ni * 8 + g;
                bf[ni][0] = Vs[col * VS2 + kp0 + t];
                bf[ni][1] = Vs[col * VS2 + kp0 + t + 4];
            }
            #pragma unroll
            for (int mi = 0; mi < 2; mi++)
                #pragma unroll
                for (int ni = 0; ni < 4; ni++)
                    mma16(acc[mi][ni], af[mi], bf[ni]);
        }
    }

    __half* yb = g_y + ((size_t)b * TT) * CC + h * DH;
    #pragma unroll
    for (int mi = 0; mi < 2; mi++)
        #pragma unroll
        for (int ni = 0; ni < 4; ni++) {
            int r0  = qt + mw * 32 + mi * 16 + g;
            int col = nw * 32 + ni * 8 + 2 * t;
            *(__half2*)(yb + (size_t)r0       * CC + col) =
                __floats2half2_rn(acc[mi][ni][0], acc[mi][ni][1]);
            *(__half2*)(yb + (size_t)(r0 + 8) * CC + col) =
                __floats2half2_rn(acc[mi][ni][2], acc[mi][ni][3]);
        }
}

// ---------------- embedding ----------------
__global__ void embed_k(const int* __restrict__ idx, const float* __restrict__ tok,
                        const float* __restrict__ pos) {
    int i = blockIdx.x * blockDim.x + threadIdx.x;
    int m = i / CC, c = i - m * CC;
    int t = m & (TT - 1);
    g_x[i] = tok[idx[m] * CC + c] + pos[t * CC + c];
}

// ---------------- layernorm (fp32 in, __half out) ----------------
__global__ void ln_k(const float* __restrict__ in, const float* __restrict__ gam,
                     const float* __restrict__ bet, __half* __restrict__ out) {
    __shared__ float sm[8];
    int row = blockIdx.x;
    const float* x = in + (size_t)row * CC;
    int t = threadIdx.x;
    float v0 = x[t], v1 = x[t + 256];
    float mean = block_reduce_sum(v0 + v1, sm) * (1.0f / CC);
    float d0 = v0 - mean, d1 = v1 - mean;
    float var = block_reduce_sum(d0 * d0 + d1 * d1, sm) * (1.0f / CC);
    float rstd = rsqrtf(var + 1e-5f);
    __half* o = out + (size_t)row * CC;
    o[t]       = __float2half(d0 * rstd * gam[t]       + bet[t]);
    o[t + 256] = __float2half(d1 * rstd * gam[t + 256] + bet[t + 256]);
}

// ---------------- host orchestration ----------------
extern "C" void kernel_launch(void* const* d_in, const int* in_sizes, int n_in,
                              void* d_out, int out_size) {
    const int*   idx  = (const int*)  d_in[0];
    const float* tok  = (const float*)d_in[1];
    const float* pos  = (const float*)d_in[2];
    const float* ln1g = (const float*)d_in[3];
    const float* ln1b = (const float*)d_in[4];
    const float* Wq   = (const float*)d_in[5];
    const float* bq   = (const float*)d_in[6];
    const float* Wk   = (const float*)d_in[7];
    const float* bk   = (const float*)d_in[8];
    const float* Wv   = (const float*)d_in[9];
    const float* bv   = (const float*)d_in[10];
    const float* Wp   = (const float*)d_in[11];
    const float* bp   = (const float*)d_in[12];
    const float* ln2g = (const float*)d_in[13];
    const float* ln2b = (const float*)d_in[14];
    const float* W1   = (const float*)d_in[15];
    const float* b1   = (const float*)d_in[16];
    const float* W2   = (const float*)d_in[17];
    const float* b2   = (const float*)d_in[18];
    const float* lnfg = (const float*)d_in[19];
    const float* lnfb = (const float*)d_in[20];
    const float* Wh   = (const float*)d_in[21];
    float* out = (float*)d_out;

    float *px;
    __half *pxn, *pqh, *pkh, *pvt, *py, *ph;
    uint32_t *pwq, *pwk, *pwv, *pwp, *pw1, *pw2, *pwh;
    cudaGetSymbolAddress((void**)&px,  g_x);
    cudaGetSymbolAddress((void**)&pxn, g_xn);
    cudaGetSymbolAddress((void**)&pqh, g_qh);
    cudaGetSymbolAddress((void**)&pkh, g_kh);
    cudaGetSymbolAddress((void**)&pvt, g_vt);
    cudaGetSymbolAddress((void**)&py,  g_y);
    cudaGetSymbolAddress((void**)&ph,  g_h);
    cudaGetSymbolAddress((void**)&pwq, g_wq);
    cudaGetSymbolAddress((void**)&pwk, g_wk);
    cudaGetSymbolAddress((void**)&pwv, g_wv);
    cudaGetSymbolAddress((void**)&pwp, g_wp);
    cudaGetSymbolAddress((void**)&pw1, g_w1);
    cudaGetSymbolAddress((void**)&pw2, g_w2);
    cudaGetSymbolAddress((void**)&pwh, g_wh);

    cudaFuncSetAttribute(hgemm_k<false,0>,
                         cudaFuncAttributeMaxDynamicSharedMemorySize, GEMMH_SMEM);
    cudaFuncSetAttribute(hgemm_k<false,1>,
                         cudaFuncAttributeMaxDynamicSharedMemorySize, GEMMH_SMEM);
    cudaFuncSetAttribute(hgemm_k<false,2>,
                         cudaFuncAttributeMaxDynamicSharedMemorySize, GEMMH_SMEM);
    cudaFuncSetAttribute(hgemm_k<true,1>,
                         cudaFuncAttributeMaxDynamicSharedMemorySize, GEMMH_SMEM);
    cudaFuncSetAttribute(attn_scores_k,
                         cudaFuncAttributeMaxDynamicSharedMemorySize, SC_SMEM);
    cudaFuncSetAttribute(attn_pv_k,
                         cudaFuncAttributeMaxDynamicSharedMemorySize, PV_SMEM);

    // pack weights to fp16 k-pair format
    for (int l = 0; l < 2; l++) {
        size_t wo  = (size_t)l * CC * CC;
        size_t wpo = (size_t)l * (CC / 2) * CC;
        pack_w_k<<<(CC / 2 * CC + 255) / 256, 256>>>(Wq + wo, pwq + wpo, CC, CC);
        pack_w_k<<<(CC / 2 * CC + 255) / 256, 256>>>(Wk + wo, pwk + wpo, CC, CC);
        pack_w_k<<<(CC / 2 * CC + 255) / 256, 256>>>(Wv + wo, pwv + wpo, CC, CC);
        pack_w_k<<<(CC / 2 * CC + 255) / 256, 256>>>(Wp + wo, pwp + wpo, CC, CC);
        pack_w_k<<<(CC / 2 * CF + 255) / 256, 256>>>(W1 + (size_t)l * CC * CF,
                                                     pw1 + (size_t)l * (CC / 2) * CF, CC, CF);
        pack_w_k<<<(CF / 2 * CC + 255) / 256, 256>>>(W2 + (size_t)l * CF * CC,
                                                     pw2 + (size_t)l * (CF / 2) * CC, CF, CC);
    }
    pack_w_k<<<(CC / 2 * VV + 255) / 256, 256>>>(Wh, pwh, CC, VV);

    embed_k<<<(MTOK * CC) / 256, 256>>>(idx, tok, pos);

    dim3 gCC(CC / 128, MTOK / 128);     // (4, 32)
    dim3 gCF(CF / 128, MTOK / 128);     // (16, 32)
    dim3 gS(4, 4, BB * HH);             // scores: 128x128 tiles
    dim3 gPV(4, BB * HH);               // pv: 128-row tiles

    for (int step = 0; step < NSTEPS; step++) {
        for (int l = 0; l < 2; l++) {
            size_t wpo = (size_t)l * (CC / 2) * CC;
            size_t bo  = (size_t)l * CC;
            size_t b1o = (size_t)l * CF;

            ln_k<<<MTOK, 256>>>(px, ln1g + bo, ln1b + bo, pxn);
            hgemm_k<false,1><<<gCC, 256, GEMMH_SMEM>>>(
                pxn, pwq + wpo, bq + bo, nullptr, pqh, MTOK, CC, CC);
            hgemm_k<false,1><<<gCC, 256, GEMMH_SMEM>>>(
                pxn, pwk + wpo, bk + bo, nullptr, pkh, MTOK, CC, CC);
            hgemm_k<false,2><<<gCC, 256, GEMMH_SMEM>>>(
                pxn, pwv + wpo, bv + bo, nullptr, pvt, MTOK, CC, CC);
            attn_scores_k<<<gS, 256, SC_SMEM>>>();
            softmax_k<<<BB * HH * TT, 256>>>();
            attn_pv_k<<<gPV, 256, PV_SMEM>>>();
            // x = x + y @ Wp + bp
            hgemm_k<false,0><<<gCC, 256, GEMMH_SMEM>>>(
                py, pwp + wpo, bp + bo, px, px, MTOK, CC, CC);

            ln_k<<<MTOK, 256>>>(px, ln2g + bo, ln2b + bo, pxn);
            hgemm_k<true,1><<<gCF, 256, GEMMH_SMEM>>>(
                pxn, pw1 + (size_t)l * (CC / 2) * CF, b1 + b1o, nullptr, ph, MTOK, CF, CC);
            // x = x + h @ W2 + b2
            hgemm_k<false,0><<<gCC, 256, GEMMH_SMEM>>>(
                ph, pw2 + (size_t)l * (CF / 2) * CC, b2 + bo, px, px, MTOK, CC, CF);
        }
    }

    ln_k<<<MTOK, 256>>>(px, lnfg, lnfb, pxn);
    hgemm_k<false,0><<<dim3(VV / 128, MTOK / 128), 256, GEMMH_SMEM>>>(
        pxn, pwh, nullptr, nullptr, out, MTOK, VV, CC);
}

// round 15
// speedup vs baseline: 1.6742x; 1.2589x over previous
#include <cuda_runtime.h>
#include <cuda_fp16.h>
#include <cstdint>
#include <math.h>

#define BB 8
#define TT 512
#define CC 512
#define HH 8
#define DH 64
#define CF 2048
#define MTOK (BB*TT)      // 4096
#define VV 512
#define NSTEPS 4
#define C3 1536
#define ATT_SCALE 0.125f  // 1/sqrt(64)

// ---------------- scratch (device globals) ----------------
__device__ float  g_x [MTOK*CC];
__device__ __half g_xn[MTOK*CC];
__device__ __half g_qh[MTOK*CC];
__device__ __half g_kh[MTOK*CC];
__device__ __half g_vt[(size_t)BB*HH*DH*TT];   // V transposed: [z][dh][token]
__device__ __half g_y [MTOK*CC];
__device__ __half g_h [MTOK*CF];
// fp16 k-pair-packed weights: u32[kp*N+n] = (W[2kp][n], W[2kp+1][n])
__device__ uint32_t g_wqkv[2*(CC/2)*C3];
__device__ float    g_bqkv[2*C3];
__device__ uint32_t g_wp[2*(CC/2)*CC];
__device__ uint32_t g_w1[2*(CC/2)*CF];
__device__ uint32_t g_w2[2*(CF/2)*CC];
__device__ uint32_t g_wh[(CC/2)*VV];

// ======================= helpers ==============================
__device__ __forceinline__ uint32_t smem_u32(const void* p) {
    uint32_t a;
    asm("{ .reg .u64 t; cvta.to.shared.u64 t, %1; cvt.u32.u64 %0, t; }"
        : "=r"(a) : "l"(p));
    return a;
}
__device__ __forceinline__ void cp_async16(uint32_t dst, const void* src) {
    asm volatile("cp.async.cg.shared.global [%0], [%1], 16;" :: "r"(dst), "l"(src));
}
__device__ __forceinline__ void cp_commit() {
    asm volatile("cp.async.commit_group;" ::: "memory");
}
template <int N>
__device__ __forceinline__ void cp_wait() {
    asm volatile("cp.async.wait_group %0;" :: "n"(N) : "memory");
}
// fp16 m16n8k16, fp32 accumulate
__device__ __forceinline__ void mma16(float* c, const uint32_t* a, const uint32_t* b) {
    asm volatile(
        "mma.sync.aligned.m16n8k16.row.col.f32.f16.f16.f32 "
        "{%0,%1,%2,%3}, {%4,%5,%6,%7}, {%8,%9}, {%0,%1,%2,%3};"
        : "+f"(c[0]), "+f"(c[1]), "+f"(c[2]), "+f"(c[3])
        : "r"(a[0]), "r"(a[1]), "r"(a[2]), "r"(a[3]), "r"(b[0]), "r"(b[1]));
}

// ---------------- weight packing ----------------
__global__ void pack_w_k(const float* __restrict__ W, uint32_t* __restrict__ dst,
                         int K, int N) {
    int i = blockIdx.x * 256 + threadIdx.x;
    if (i >= (K / 2) * N) return;
    int kp = i / N, n = i - kp * N;
    __half lo = __float2half(W[(size_t)(2 * kp)     * N + n]);
    __half hi = __float2half(W[(size_t)(2 * kp + 1) * N + n]);
    dst[i] = (uint32_t)__half_as_ushort(lo) | ((uint32_t)__half_as_ushort(hi) << 16);
}
// fused QKV weights: [l][(CC/2)][1536], cols 0-511 Wq, 512-1023 Wk, 1024+ Wv
__global__ void pack_qkv_k(const float* __restrict__ Wq, const float* __restrict__ Wk,
                           const float* __restrict__ Wv) {
    int i = blockIdx.x * 256 + threadIdx.x;          // over 2*(CC/2)*C3
    if (i >= 2 * (CC / 2) * C3) return;
    int l = i / ((CC / 2) * C3), rem = i % ((CC / 2) * C3);
    int kp = rem / C3, n = rem % C3;
    const float* src; int nn;
    if (n < CC) { src = Wq; nn = n; }
    else if (n < 2 * CC) { src = Wk; nn = n - CC; }
    else { src = Wv; nn = n - 2 * CC; }
    size_t base = (size_t)l * CC * CC + (size_t)(2 * kp) * CC + nn;
    __half lo = __float2half(src[base]);
    __half hi = __float2half(src[base + CC]);
    g_wqkv[i] = (uint32_t)__half_as_ushort(lo) | ((uint32_t)__half_as_ushort(hi) << 16);
}
__global__ void pack_bqkv_k(const float* __restrict__ bq, const float* __restrict__ bk,
                            const float* __restrict__ bv) {
    int i = blockIdx.x * 256 + threadIdx.x;          // over 2*CC
    if (i >= 2 * CC) return;
    int l = i / CC, n = i % CC;
    g_bqkv[l * C3 + n]          = bq[i];
    g_bqkv[l * C3 + CC + n]     = bk[i];
    g_bqkv[l * C3 + 2 * CC + n] = bv[i];
}

// ============ dense fp16 GEMM: out = epi(A@W + bias + res) =================
// OUT modes: 0 = fp32, 1 = fp16 row-major, 3 = QKV routing (N=1536)
#define AS2 20
#define BS2 136
#define GEMMH_SMEM (2*128*AS2*4 + 2*16*BS2*4)   // 37888 B

template <bool GELU, int OUTMODE>
__global__ void __launch_bounds__(256, 2)
hgemm_k(const __half* __restrict__ A, const uint32_t* __restrict__ Wp,
        const float* __restrict__ bias, const float* __restrict__ res,
        void* __restrict__ outv, int M, int N, int K) {
    extern __shared__ char dsm[];
    uint32_t* As = (uint32_t*)dsm;                 // [2][128][AS2]
    uint32_t* Bs = As + 2 * 128 * AS2;             // [2][16][BS2]

    int tid = threadIdx.x;
    int wid = tid >> 5, lane = tid & 31;
    int g = lane >> 2, t = lane & 3;
    int mw = wid >> 2, nw = wid & 3;
    int m0 = blockIdx.y * 128, n0 = blockIdx.x * 128;

    auto loadA = [&](int chunk, int buf) {
        const __half* src = A + (size_t)m0 * K + chunk * 32;
        uint32_t* dst = As + buf * 128 * AS2;
        #pragma unroll
        for (int i = 0; i < 2; i++) {
            int c = tid + i * 256;
            int m = c >> 2, s = c & 3;
            cp_async16(smem_u32(dst + m * AS2 + s * 4),
                       src + (size_t)m * K + s * 8);
        }
    };
    auto loadB = [&](int chunk, int buf) {
        const uint32_t* src = Wp + (size_t)(chunk * 16) * N + n0;
        uint32_t* dst = Bs + buf * 16 * BS2;
        #pragma unroll
        for (int i = 0; i < 2; i++) {
            int c = tid + i * 256;
            int k = c >> 5, s = c & 31;
            cp_async16(smem_u32(dst + k * BS2 + s * 4),
                       src + (size_t)k * N + s * 4);
        }
    };

    float acc[4][4][4];
    #pragma unroll
    for (int mi = 0; mi < 4; mi++)
        #pragma unroll
        for (int ni = 0; ni < 4; ni++)
            #pragma unroll
            for (int q = 0; q < 4; q++) acc[mi][ni][q] = 0.0f;

    const int nch = K >> 5;
    loadA(0, 0); loadB(0, 0); cp_commit();

    for (int i = 0; i < nch; i++) {
        int buf = i & 1;
        if (i + 1 < nch) {
            loadA(i + 1, buf ^ 1); loadB(i + 1, buf ^ 1); cp_commit();
            cp_wait<1>();
        } else {
            cp_wait<0>();
        }
        __syncthreads();
        const uint32_t* Ab = As + buf * 128 * AS2;
        const uint32_t* Bb = Bs + buf * 16 * BS2;
        #pragma unroll
        for (int s2 = 0; s2 < 2; s2++) {
            int kp0 = s2 * 8;
            uint32_t af[4][4], bf[4][2];
            #pragma unroll
            for (int mi = 0; mi < 4; mi++) {
                int row = mw * 64 + mi * 16;
                af[mi][0] = Ab[(row + g)     * AS2 + kp0 + t];
                af[mi][1] = Ab[(row + 8 + g) * AS2 + kp0 + t];
                af[mi][2] = Ab[(row + g)     * AS2 + kp0 + t + 4];
                af[mi][3] = Ab[(row + 8 + g) * AS2 + kp0 + t + 4];
            }
            #pragma unroll
            for (int ni = 0; ni < 4; ni++) {
                int col = nw * 32 + ni * 8 + g;
                bf[ni][0] = Bb[(kp0 + t)     * BS2 + col];
                bf[ni][1] = Bb[(kp0 + t + 4) * BS2 + col];
            }
            #pragma unroll
            for (int mi = 0; mi < 4; mi++)
                #pragma unroll
                for (int ni = 0; ni < 4; ni++)
                    mma16(acc[mi][ni], af[mi], bf[ni]);
        }
        __syncthreads();
    }

    // epilogue
    #pragma unroll
    for (int mi = 0; mi < 4; mi++) {
        #pragma unroll
        for (int ni = 0; ni < 4; ni++) {
            int r0  = m0 + mw * 64 + mi * 16 + g;
            int col = n0 + nw * 32 + ni * 8 + 2 * t;
            #pragma unroll
            for (int hh = 0; hh < 2; hh++) {
                int r = r0 + 8 * hh;
                #pragma unroll
                for (int q = 0; q < 2; q++) {
                    float v = acc[mi][ni][2 * hh + q];
                    int c = col + q;
                    if (bias) v += bias[c];
                    if (res)  v += res[(size_t)r * N + c];
                    if (GELU) v = 0.5f * v * (1.0f + erff(v * 0.70710678118654752f));
                    if (OUTMODE == 1) {
                        ((__half*)outv)[(size_t)r * N + c] = __float2half(v);
                    } else if (OUTMODE == 3) {
                        __half hv = __float2half(v);
                        if (c < CC) {
                            g_qh[(size_t)r * CC + c] = hv;
                        } else if (c < 2 * CC) {
                            g_kh[(size_t)r * CC + (c - CC)] = hv;
                        } else {
                            int cv = c - 2 * CC;
                            int h8 = cv >> 6, dh = cv & 63;
                            int b = r >> 9, tok = r & (TT - 1);
                            g_vt[(((size_t)(b * HH + h8) * DH) + dh) * TT + tok] = hv;
                        }
                    } else {
                        ((float*)outv)[(size_t)r * N + c] = v;
                    }
                }
            }
        }
    }
}

// ============ fused attention: S=QK^T, softmax, Y=PV — one kernel ==========
// CTA: 64 q-rows x ALL 512 keys for one (b,h). 8 warps.
// Phase1: warp w owns 64 score-cols; S fully in regs (acc[4][8][4]).
// Softmax: exact (full row resident), cross-warp reduce via smem.
// P (half) overwrites the K smem region; Phase2: PV fp16 mma 4x2 warp grid.
#define FQS 36     // u32 stride Q/K rows (32 data + 4 pad)
#define FPS 268    // u32 stride P / V^T rows (256 data + 12 pad)
#define OFF_Q 0
#define OFF_K (64*FQS*4)                           // 9216
#define OFF_V (OFF_K + 512*FQS*4)                  // 82944
#define OFF_R (OFF_V + 64*FPS*4)                   // 151552
#define ATT_SMEM (OFF_R + 4096)                    // 155648

__global__ void __launch_bounds__(256, 1)
attn_fused_k() {
    extern __shared__ char dsm[];
    uint32_t* Qs = (uint32_t*)(dsm + OFF_Q);       // [64][FQS]
    uint32_t* Ks = (uint32_t*)(dsm + OFF_K);       // [512][FQS]; later P [64][FPS]
    uint32_t* Vs = (uint32_t*)(dsm + OFF_V);       // [64][FPS]
    float* red_max = (float*)(dsm + OFF_R);        // [8][64]
    float* red_sum = red_max + 512;                // [8][64]

    int tid = threadIdx.x;
    int w = tid >> 5, lane = tid & 31;
    int g = lane >> 2, t = lane & 3;
    int z = blockIdx.y;                            // b*H + h
    int b = z >> 3, h = z & 7;
    int qt = blockIdx.x * 64;

    const __half* qb = g_qh + ((size_t)(b * TT + qt)) * CC + h * DH;
    const __half* kb = g_kh + ((size_t)b * TT) * CC + h * DH;
    const __half* vt = g_vt + (size_t)z * DH * TT;

    // Q: 64 rows x 8 segs of 8 halfs = 512 tasks
    #pragma unroll
    for (int i = 0; i < 2; i++) {
        int c = tid + i * 256;
        int r = c >> 3, s = c & 7;
        cp_async16(smem_u32(Qs + r * FQS + s * 4), qb + (size_t)r * CC + s * 8);
    }
    // K: 512 rows x 8 segs = 4096 tasks
    #pragma unroll
    for (int i = 0; i < 16; i++) {
        int c = tid + i * 256;
        int r = c >> 3, s = c & 7;
        cp_async16(smem_u32(Ks + r * FQS + s * 4), kb + (size_t)r * CC + s * 8);
    }
    // V^T: 64 dh-rows x 64 segs = 4096 tasks
    #pragma unroll
    for (int i = 0; i < 16; i++) {
        int c = tid + i * 256;
        int r = c >> 6, s = c & 63;
        cp_async16(smem_u32(Vs + r * FPS + s * 4), vt + (size_t)r * TT + s * 8);
    }
    cp_commit(); cp_wait<0>();
    __syncthreads();

    // ---- Phase 1: S = Q @ K^T * scale (warp w: cols w*64..w*64+63) ----
    float acc[4][8][4];
    #pragma unroll
    for (int mi = 0; mi < 4; mi++)
        #pragma unroll
        for (int nf = 0; nf < 8; nf++)
            #pragma unroll
            for (int q = 0; q < 4; q++) acc[mi][nf][q] = 0.0f;

    #pragma unroll
    for (int s2 = 0; s2 < 4; s2++) {
        int kp0 = s2 * 8;
        uint32_t af[4][4], bf[8][2];
        #pragma unroll
        for (int mi = 0; mi < 4; mi++) {
            int row = mi * 16;
            af[mi][0] = Qs[(row + g)     * FQS + kp0 + t];
            af[mi][1] = Qs[(row + 8 + g) * FQS + kp0 + t];
            af[mi][2] = Qs[(row + g)     * FQS + kp0 + t + 4];
            af[mi][3] = Qs[(row + 8 + g) * FQS + kp0 + t + 4];
        }
        #pragma unroll
        for (int nf = 0; nf < 8; nf++) {
            int col = w * 64 + nf * 8 + g;
            bf[nf][0] = Ks[col * FQS + kp0 + t];
            bf[nf][1] = Ks[col * FQS + kp0 + t + 4];
        }
        #pragma unroll
        for (int mi = 0; mi < 4; mi++)
            #pragma unroll
            for (int nf = 0; nf < 8; nf++)
                mma16(acc[mi][nf], af[mi], bf[nf]);
    }

    // scale + local row max (rows mi*16+g and mi*16+8+g)
    float lmx0[4], lmx1[4];
    #pragma unroll
    for (int mi = 0; mi < 4; mi++) { lmx0[mi] = -1e30f; lmx1[mi] = -1e30f; }
    #pragma unroll
    for (int mi = 0; mi < 4; mi++)
        #pragma unroll
        for (int nf = 0; nf < 8; nf++) {
            acc[mi][nf][0] *= ATT_SCALE; acc[mi][nf][1] *= ATT_SCALE;
            acc[mi][nf][2] *= ATT_SCALE; acc[mi][nf][3] *= ATT_SCALE;
            lmx0[mi] = fmaxf(lmx0[mi], fmaxf(acc[mi][nf][0], acc[mi][nf][1]));
            lmx1[mi] = fmaxf(lmx1[mi], fmaxf(acc[mi][nf][2], acc[mi][nf][3]));
        }
    #pragma unroll
    for (int mi = 0; mi < 4; mi++) {
        lmx0[mi] = fmaxf(lmx0[mi], __shfl_xor_sync(0xffffffffu, lmx0[mi], 1));
        lmx0[mi] = fmaxf(lmx0[mi], __shfl_xor_sync(0xffffffffu, lmx0[mi], 2));
        lmx1[mi] = fmaxf(lmx1[mi], __shfl_xor_sync(0xffffffffu, lmx1[mi], 1));
        lmx1[mi] = fmaxf(lmx1[mi], __shfl_xor_sync(0xffffffffu, lmx1[mi], 2));
    }
    if (t == 0) {
        #pragma unroll
        for (int mi = 0; mi < 4; mi++) {
            red_max[w * 64 + mi * 16 + g]     = lmx0[mi];
            red_max[w * 64 + mi * 16 + 8 + g] = lmx1[mi];
        }
    }
    __syncthreads();
    float mx0[4], mx1[4];
    #pragma unroll
    for (int mi = 0; mi < 4; mi++) {
        float a = -1e30f, c2 = -1e30f;
        #pragma unroll
        for (int wi = 0; wi < 8; wi++) {
            a  = fmaxf(a,  red_max[wi * 64 + mi * 16 + g]);
            c2 = fmaxf(c2, red_max[wi * 64 + mi * 16 + 8 + g]);
        }
        mx0[mi] = a; mx1[mi] = c2;
    }

    // exp + local sums
    float ls0[4], ls1[4];
    #pragma unroll
    for (int mi = 0; mi < 4; mi++) { ls0[mi] = 0.0f; ls1[mi] = 0.0f; }
    #pragma unroll
    for (int mi = 0; mi < 4; mi++)
        #pragma unroll
        for (int nf = 0; nf < 8; nf++) {
            acc[mi][nf][0] = __expf(acc[mi][nf][0] - mx0[mi]);
            acc[mi][nf][1] = __expf(acc[mi][nf][1] - mx0[mi]);
            acc[mi][nf][2] = __expf(acc[mi][nf][2] - mx1[mi]);
            acc[mi][nf][3] = __expf(acc[mi][nf][3] - mx1[mi]);
            ls0[mi] += acc[mi][nf][0] + acc[mi][nf][1];
            ls1[mi] += acc[mi][nf][2] + acc[mi][nf][3];
        }
    #pragma unroll
    for (int mi = 0; mi < 4; mi++) {
        ls0[mi] += __shfl_xor_sync(0xffffffffu, ls0[mi], 1);
        ls0[mi] += __shfl_xor_sync(0xffffffffu, ls0[mi], 2);
        ls1[mi] += __shfl_xor_sync(0xffffffffu, ls1[mi], 1);
        ls1[mi] += __shfl_xor_sync(0xffffffffu, ls1[mi], 2);
    }
    if (t == 0) {
        #pragma unroll
        for (int mi = 0; mi < 4; mi++) {
            red_sum[w * 64 + mi * 16 + g]     = ls0[mi];
            red_sum[w * 64 + mi * 16 + 8 + g] = ls1[mi];
        }
    }
    __syncthreads();

    // write P = exp/sum into K region as half [64 rows][512], stride FPS u32
    __half* Pk = (__half*)Ks;
    #pragma unroll
    for (int mi = 0; mi < 4; mi++) {
        float s0 = 0.0f, s1 = 0.0f;
        #pragma unroll
        for (int wi = 0; wi < 8; wi++) {
            s0 += red_sum[wi * 64 + mi * 16 + g];
            s1 += red_sum[wi * 64 + mi * 16 + 8 + g];
        }
        float i0 = 1.0f / s0, i1 = 1.0f / s1;
        #pragma unroll
        for (int nf = 0; nf < 8; nf++) {
            int col = w * 64 + nf * 8 + 2 * t;
            *(__half2*)(Pk + (size_t)(mi * 16 + g)     * (FPS * 2) + col) =
                __floats2half2_rn(acc[mi][nf][0] * i0, acc[mi][nf][1] * i0);
            *(__half2*)(Pk + (size_t)(mi * 16 + 8 + g) * (FPS * 2) + col) =
                __floats2half2_rn(acc[mi][nf][2] * i1, acc[mi][nf][3] * i1);
        }
    }
    __syncthreads();

    // ---- Phase 2: Y = P @ V  (warp grid 4m x 2n, warp tile 16x32) ----
    uint32_t* Pu = Ks;                             // u32 view [64][FPS]
    int mw = w & 3, nw = w >> 2;
    float o[4][4];
    #pragma unroll
    for (int ni = 0; ni < 4; ni++)
        #pragma unroll
        for (int q = 0; q < 4; q++) o[ni][q] = 0.0f;

    #pragma unroll 8
    for (int ks = 0; ks < 32; ks++) {
        int kp0 = ks * 8;
        uint32_t af[4], bf[4][2];
        int row = mw * 16;
        af[0] = Pu[(row + g)     * FPS + kp0 + t];
        af[1] = Pu[(row + 8 + g) * FPS + kp0 + t];
        af[2] = Pu[(row + g)     * FPS + kp0 + t + 4];
        af[3] = Pu[(row + 8 + g) * FPS + kp0 + t + 4];
        #pragma unroll
        for (int ni = 0; ni < 4; ni++) {
            int col = nw * 32 + ni * 8 + g;
            bf[ni][0] = Vs[col * FPS + kp0 + t];
            bf[ni][1] = Vs[col * FPS + kp0 + t + 4];
        }
        #pragma unroll
        for (int ni = 0; ni < 4; ni++)
            mma16(o[ni], af, bf[ni]);
    }

    __half* yb = g_y + ((size_t)(b * TT + qt)) * CC + h * DH;
    #pragma unroll
    for (int ni = 0; ni < 4; ni++) {
        int r0  = mw * 16 + g;
        int col = nw * 32 + ni * 8 + 2 * t;
        *(__half2*)(yb + (size_t)r0       * CC + col) =
            __floats2half2_rn(o[ni][0], o[ni][1]);
        *(__half2*)(yb + (size_t)(r0 + 8) * CC + col) =
            __floats2half2_rn(o[ni][2], o[ni][3]);
    }
}

// ---------------- block reductions / LN / embed ----------------
__device__ __forceinline__ float block_reduce_sum(float v, float* sm) {
    #pragma unroll
    for (int o = 16; o; o >>= 1) v += __shfl_xor_sync(0xffffffffu, v, o);
    int w = threadIdx.x >> 5;
    if ((threadIdx.x & 31) == 0) sm[w] = v;
    __syncthreads();
    if (threadIdx.x < 32) {
        float x = (threadIdx.x < 8) ? sm[threadIdx.x] : 0.0f;
        #pragma unroll
        for (int o = 4; o; o >>= 1) x += __shfl_xor_sync(0xffffffffu, x, o);
        if (threadIdx.x == 0) sm[0] = x;
    }
    __syncthreads();
    float r = sm[0];
    __syncthreads();
    return r;
}

__global__ void embed_k(const int* __restrict__ idx, const float* __restrict__ tok,
                        const float* __restrict__ pos) {
    int i = blockIdx.x * blockDim.x + threadIdx.x;
    int m = i / CC, c = i - m * CC;
    int t = m & (TT - 1);
    g_x[i] = tok[idx[m] * CC + c] + pos[t * CC + c];
}

__global__ void ln_k(const float* __restrict__ in, const float* __restrict__ gam,
                     const float* __restrict__ bet, __half* __restrict__ out) {
    __shared__ float sm[8];
    int row = blockIdx.x;
    const float* x = in + (size_t)row * CC;
    int t = threadIdx.x;
    float v0 = x[t], v1 = x[t + 256];
    float mean = block_reduce_sum(v0 + v1, sm) * (1.0f / CC);
    float d0 = v0 - mean, d1 = v1 - mean;
    float var = block_reduce_sum(d0 * d0 + d1 * d1, sm) * (1.0f / CC);
    float rstd = rsqrtf(var + 1e-5f);
    __half* o = out + (size_t)row * CC;
    o[t]       = __float2half(d0 * rstd * gam[t]       + bet[t]);
    o[t + 256] = __float2half(d1 * rstd * gam[t + 256] + bet[t + 256]);
}

// ---------------- host orchestration ----------------
extern "C" void kernel_launch(void* const* d_in, const int* in_sizes, int n_in,
                              void* d_out, int out_size) {
    const int*   idx  = (const int*)  d_in[0];
    const float* tok  = (const float*)d_in[1];
    const float* pos  = (const float*)d_in[2];
    const float* ln1g = (const float*)d_in[3];
    const float* ln1b = (const float*)d_in[4];
    const float* Wq   = (const float*)d_in[5];
    const float* bq   = (const float*)d_in[6];
    const float* Wk   = (const float*)d_in[7];
    const float* bk   = (const float*)d_in[8];
    const float* Wv   = (const float*)d_in[9];
    const float* bv   = (const float*)d_in[10];
    const float* Wp   = (const float*)d_in[11];
    const float* bp   = (const float*)d_in[12];
    const float* ln2g = (const float*)d_in[13];
    const float* ln2b = (const float*)d_in[14];
    const float* W1   = (const float*)d_in[15];
    const float* b1   = (const float*)d_in[16];
    const float* W2   = (const float*)d_in[17];
    const float* b2   = (const float*)d_in[18];
    const float* lnfg = (const float*)d_in[19];
    const float* lnfb = (const float*)d_in[20];
    const float* Wh   = (const float*)d_in[21];
    float* out = (float*)d_out;

    float *px, *pbqkv;
    __half *pxn, *py, *ph;
    uint32_t *pwqkv, *pwp, *pw1, *pw2, *pwh;
    cudaGetSymbolAddress((void**)&px,    g_x);
    cudaGetSymbolAddress((void**)&pxn,   g_xn);
    cudaGetSymbolAddress((void**)&py,    g_y);
    cudaGetSymbolAddress((void**)&ph,    g_h);
    cudaGetSymbolAddress((void**)&pwqkv, g_wqkv);
    cudaGetSymbolAddress((void**)&pbqkv, g_bqkv);
    cudaGetSymbolAddress((void**)&pwp,   g_wp);
    cudaGetSymbolAddress((void**)&pw1,   g_w1);
    cudaGetSymbolAddress((void**)&pw2,   g_w2);
    cudaGetSymbolAddress((void**)&pwh,   g_wh);

    cudaFuncSetAttribute(hgemm_k<false,0>,
                         cudaFuncAttributeMaxDynamicSharedMemorySize, GEMMH_SMEM);
    cudaFuncSetAttribute(hgemm_k<false,1>,
                         cudaFuncAttributeMaxDynamicSharedMemorySize, GEMMH_SMEM);
    cudaFuncSetAttribute(hgemm_k<false,3>,
                         cudaFuncAttributeMaxDynamicSharedMemorySize, GEMMH_SMEM);
    cudaFuncSetAttribute(hgemm_k<true,1>,
                         cudaFuncAttributeMaxDynamicSharedMemorySize, GEMMH_SMEM);
    cudaFuncSetAttribute(attn_fused_k,
                         cudaFuncAttributeMaxDynamicSharedMemorySize, ATT_SMEM);

    // weight packing
    pack_qkv_k<<<(2 * (CC / 2) * C3 + 255) / 256, 256>>>(Wq, Wk, Wv);
    pack_bqkv_k<<<(2 * CC + 255) / 256, 256>>>(bq, bk, bv);
    for (int l = 0; l < 2; l++) {
        pack_w_k<<<(CC / 2 * CC + 255) / 256, 256>>>(
            Wp + (size_t)l * CC * CC, pwp + (size_t)l * (CC / 2) * CC, CC, CC);
        pack_w_k<<<(CC / 2 * CF + 255) / 256, 256>>>(
            W1 + (size_t)l * CC * CF, pw1 + (size_t)l * (CC / 2) * CF, CC, CF);
        pack_w_k<<<(CF / 2 * CC + 255) / 256, 256>>>(
            W2 + (size_t)l * CF * CC, pw2 + (size_t)l * (CF / 2) * CC, CF, CC);
    }
    pack_w_k<<<(CC / 2 * VV + 255) / 256, 256>>>(Wh, pwh, CC, VV);

    embed_k<<<(MTOK * CC) / 256, 256>>>(idx, tok, pos);

    dim3 gQKV(C3 / 128, MTOK / 128);    // (12, 32)
    dim3 gCC(CC / 128, MTOK / 128);     // (4, 32)
    dim3 gCF(CF / 128, MTOK / 128);     // (16, 32)
    dim3 gAT(TT / 64, BB * HH);         // (8, 64)

    for (int step = 0; step < NSTEPS; step++) {
        for (int l = 0; l < 2; l++) {
            size_t wpo = (size_t)l * (CC / 2) * CC;
            size_t bo  = (size_t)l * CC;
            size_t b1o = (size_t)l * CF;

            ln_k<<<MTOK, 256>>>(px, ln1g + bo, ln1b + bo, pxn);
            hgemm_k<false,3><<<gQKV, 256, GEMMH_SMEM>>>(
                pxn, pwqkv + (size_t)l * (CC / 2) * C3, pbqkv + (size_t)l * C3,
                nullptr, nullptr, MTOK, C3, CC);
            attn_fused_k<<<gAT, 256, ATT_SMEM>>>();
            // x = x + y @ Wp + bp
            hgemm_k<false,0><<<gCC, 256, GEMMH_SMEM>>>(
                py, pwp + wpo, bp + bo, px, px, MTOK, CC, CC);

            ln_k<<<MTOK, 256>>>(px, ln2g + bo, ln2b + bo, pxn);
            hgemm_k<true,1><<<gCF, 256, GEMMH_SMEM>>>(
                pxn, pw1 + (size_t)l * (CC / 2) * CF, b1 + b1o, nullptr, ph, MTOK, CF, CC);
            // x = x + h @ W2 + b2
            hgemm_k<false,0><<<gCC, 256, GEMMH_SMEM>>>(
                ph, pw2 + (size_t)l * (CF / 2) * CC, b2 + bo, px, px, MTOK, CC, CF);
        }
    }

    ln_k<<<MTOK, 256>>>(px, lnfg, lnfb, pxn);
    hgemm_k<false,0><<<dim3(VV / 128, MTOK / 128), 256, GEMMH_SMEM>>>(
        pxn, pwh, nullptr, nullptr, out, MTOK, VV, CC);
}